// round 14
// baseline (speedup 1.0000x reference)
#include <cuda_runtime.h>
#include <math.h>

#define BB   256

// out layout: value [B,32,32,32] | weight [B,32,32] | wp [B,32,32]
#define WOFF      (8388608ull)
#define WPOFF     (8650752ull)

typedef unsigned long long ull;

__device__ float g_M [128 * 128];
__device__ float g_Mp[128 * 128];
__device__ float g_U [BB * 32 * 64];
__device__ float g_V [BB * 32 * 64];
__device__ unsigned g_W2h[64 * 32];
__device__ unsigned g_W2l[64 * 32];

// ---- packed f32x2 helpers ----
__device__ __forceinline__ ull pk2(float v) {
    ull r; asm("mov.b64 %0, {%1, %1};" : "=l"(r) : "f"(v)); return r;
}
__device__ __forceinline__ ull ffma2(ull a, ull b, ull c) {
    ull d; asm("fma.rn.f32x2 %0, %1, %2, %3;" : "=l"(d) : "l"(a), "l"(b), "l"(c)); return d;
}
__device__ __forceinline__ float2 upk2(ull v) {
    float2 f; asm("mov.b64 {%0, %1}, %2;" : "=f"(f.x), "=f"(f.y) : "l"(v)); return f;
}

// ---- tf32 helpers ----
__device__ __forceinline__ unsigned tf32_of(float x) {
    unsigned r; asm("cvt.rna.tf32.f32 %0, %1;" : "=r"(r) : "f"(x)); return r;
}
__device__ __forceinline__ void mma_tf32(float d[4], const unsigned a[4],
                                         unsigned b0, unsigned b1) {
    asm("mma.sync.aligned.m16n8k8.row.col.f32.tf32.tf32.f32 "
        "{%0,%1,%2,%3}, {%4,%5,%6,%7}, {%8,%9}, {%0,%1,%2,%3};"
        : "+f"(d[0]), "+f"(d[1]), "+f"(d[2]), "+f"(d[3])
        : "r"(a[0]), "r"(a[1]), "r"(a[2]), "r"(a[3]), "r"(b0), "r"(b1));
}

__device__ __forceinline__ float warp_max(float v) {
    #pragma unroll
    for (int o = 16; o; o >>= 1) v = fmaxf(v, __shfl_xor_sync(0xffffffffu, v, o));
    return v;
}
__device__ __forceinline__ float warp_sum(float v) {
    #pragma unroll
    for (int o = 16; o; o >>= 1) v += __shfl_xor_sync(0xffffffffu, v, o);
    return v;
}

// ---------------------------------------------------------------------------
// Kernel 0 (measured ~9us): M/Mp GEMMs + W2 hi/lo split.
// ---------------------------------------------------------------------------
__global__ void k0_all(const float* __restrict__ Wq, const float* __restrict__ Wk,
                       const float* __restrict__ Wqp, const float* __restrict__ Wkp,
                       const float* __restrict__ Wf2) {
    const int bx = blockIdx.x;
    const int t  = threadIdx.x;
    if (bx >= 256) {
        int idx = (bx - 256) * 256 + t;
        float v = Wf2[idx];
        unsigned h = tf32_of(v);
        g_W2h[idx] = h;
        g_W2l[idx] = tf32_of(v - __uint_as_float(h));
        return;
    }
    __shared__ float sA[8 * 128];
    __shared__ float sB[16 * 129];
    __shared__ float sR[128 * 2];
    const int mat = bx >> 7;
    const int e0  = ((bx >> 3) & 15) * 8;
    const int c0  = (bx & 7) * 16;
    const float* A  = mat ? Wqp : Wq;
    const float* Bm = mat ? Wkp : Wk;
    float* out      = mat ? g_Mp : g_M;
    for (int i = t; i < 1024; i += 256) sA[i] = A[e0 * 128 + i];
    for (int i = t; i < 2048; i += 256) {
        int r = i >> 7, d = i & 127;
        sB[r * 129 + d] = Bm[(c0 + r) * 128 + d];
    }
    __syncthreads();
    const int kh = t >> 7, r = (t >> 4) & 7, c = t & 15;
    float acc = 0.f;
    const int d0 = kh * 64;
    #pragma unroll 8
    for (int d = 0; d < 64; ++d)
        acc = fmaf(sA[r * 128 + d0 + d], sB[c * 129 + d0 + d], acc);
    sR[(r * 16 + c) * 2 + kh] = acc;
    __syncthreads();
    if (t < 128) {
        int rr = t >> 4, cc = t & 15;
        out[(e0 + rr) * 128 + c0 + cc] = sR[t * 2] + sR[t * 2 + 1];
    }
}

// ---------------------------------------------------------------------------
// k1 staged fp32 GEMM cores (round-7 proven, untouched).
// ---------------------------------------------------------------------------
__device__ __forceinline__ void mm_chunk128(const float* __restrict__ X, int xstr, int e0,
                                            const float* __restrict__ Ws,
                                            ull acc[4][2], int r0, int l) {
    #pragma unroll 4
    for (int e = 0; e < 32; ++e) {
        ulonglong2 wv = *reinterpret_cast<const ulonglong2*>(&Ws[e * 128 + 4 * l]);
        #pragma unroll
        for (int r = 0; r < 4; ++r) {
            ull xx = pk2(X[(r0 + r) * xstr + e0 + e]);
            acc[r][0] = ffma2(xx, wv.x, acc[r][0]);
            acc[r][1] = ffma2(xx, wv.y, acc[r][1]);
        }
    }
}

__device__ __forceinline__ void mm_chunk64(const float* __restrict__ X, int e0,
                                           const float* __restrict__ Ws,
                                           ull acc[4], int r0, int l) {
    #pragma unroll 4
    for (int e = 0; e < 64; ++e) {
        ull wv = *reinterpret_cast<const ull*>(&Ws[e * 64 + 2 * l]);
        #pragma unroll
        for (int r = 0; r < 4; ++r)
            acc[r] = ffma2(pk2(X[(r0 + r) * 128 + e0 + e]), wv, acc[r]);
    }
}

__device__ __forceinline__ void store128(float* __restrict__ Y, ull acc[4][2],
                                         int r0, int l, bool do_tanh) {
    #pragma unroll
    for (int r = 0; r < 4; ++r) {
        float2 p0 = upk2(acc[r][0]);
        float2 p1 = upk2(acc[r][1]);
        float4 v = make_float4(p0.x, p0.y, p1.x, p1.y);
        if (do_tanh) { v.x = tanhf(v.x); v.y = tanhf(v.y); v.z = tanhf(v.z); v.w = tanhf(v.w); }
        *reinterpret_cast<float4*>(&Y[(r0 + r) * 128 + 4 * l]) = v;
    }
}

// ---------------------------------------------------------------------------
// Kernel 1 (round-7 exact): one block per batch. smem = 90,496 B (correct size).
// ---------------------------------------------------------------------------
#define SM1_BYTES 90496
#define SOFTMAX_SCALE 0.08838834764831843f   // 1/sqrt(128)

#define STAGE(SRC) do {                                                    \
    __syncthreads();                                                       \
    { const float4* s4 = reinterpret_cast<const float4*>(SRC);            \
      float4* d4 = reinterpret_cast<float4*>(s_Wst);                      \
      for (int i = t; i < 1024; i += 256) d4[i] = s4[i]; }                \
    __syncthreads();                                                       \
} while (0)

extern "C" __global__ void __launch_bounds__(256, 2)
k1_batch(const float* __restrict__ states, const float* __restrict__ policies,
         const float* __restrict__ actions, const float* __restrict__ states_people,
         const float* __restrict__ actions_people,
         const float* __restrict__ Wv, const float* __restrict__ Wvp,
         const float* __restrict__ Wf1, float* __restrict__ out) {
    extern __shared__ __align__(16) float sm[];
    float* s_oa  = sm;                 // 32 x 129
    float* s_oap = s_oa  + 4128;       // 32 x 129
    float* s_t   = s_oap + 4128;       // 32 x 128
    float* s_w   = s_t   + 4096;       // 32 x 32
    float* s_wp  = s_w   + 1024;       // 32 x 33
    float* s_A1  = s_wp  + 1056;       // 32 x 64  (early: sc 32x33)
    float* s_C1  = s_A1  + 2048;       // 32 x 64  (early: sp 32x33)
    float* s_Wst = s_C1  + 2048;       // 4096 floats: weight chunk buffer
    float* s_sc  = s_A1;
    float* s_sp  = s_C1;

    const int b = blockIdx.x;
    const int t = threadIdx.x;
    const int w = t >> 5, l = t & 31, r0 = 4 * w;

    const float* ac = actions  + (size_t)b * 1024;
    const float* po = policies + (size_t)b * 1024;

    float d_r[4];
    #pragma unroll
    for (int r = 0; r < 4; ++r)
        d_r[r] = po[(r0 + r) * 32 + l] - ac[(r0 + r) * 32 + l];

    {
        const float* st  = states         + (size_t)b * 32 * 96;
        const float* stp = states_people  + (size_t)b * 32 * 96;
        const float* acp = actions_people + (size_t)b * 1024;
        for (int idx = t; idx < 4096; idx += 256) {
            int i = idx >> 7, c = idx & 127;
            s_oa [i * 129 + c] = (c < 96) ? st [i * 96 + c] : ac [i * 32 + c - 96];
            s_oap[i * 129 + c] = (c < 96) ? stp[i * 96 + c] : acp[i * 32 + c - 96];
        }
    }

    // --- t = oa @ M (staged); scores -> sc ---
    {
        ull a1[4][2] = {{0,0},{0,0},{0,0},{0,0}};
        #pragma unroll 1
        for (int ck = 0; ck < 4; ++ck) {
            STAGE(g_M + ck * 4096);
            mm_chunk128(s_oa, 129, ck * 32, s_Wst, a1, r0, l);
        }
        store128(s_t, a1, r0, l, false);
        float a0 = 0, s1 = 0, s2 = 0, s3 = 0;
        #pragma unroll 4
        for (int f = 0; f < 128; ++f) {
            float oj = s_oa[l * 129 + f];
            a0 = fmaf(s_t[(r0 + 0) * 128 + f], oj, a0);
            s1 = fmaf(s_t[(r0 + 1) * 128 + f], oj, s1);
            s2 = fmaf(s_t[(r0 + 2) * 128 + f], oj, s2);
            s3 = fmaf(s_t[(r0 + 3) * 128 + f], oj, s3);
        }
        s_sc[(r0 + 0) * 33 + l] = a0;  s_sc[(r0 + 1) * 33 + l] = s1;
        s_sc[(r0 + 2) * 33 + l] = s2;  s_sc[(r0 + 3) * 33 + l] = s3;
    }

    // --- tp = oa @ Mp (staged); scores_p -> sp ---
    {
        ull a2[4][2] = {{0,0},{0,0},{0,0},{0,0}};
        #pragma unroll 1
        for (int ck = 0; ck < 4; ++ck) {
            STAGE(g_Mp + ck * 4096);
            mm_chunk128(s_oa, 129, ck * 32, s_Wst, a2, r0, l);
        }
        store128(s_t, a2, r0, l, false);
        float c0 = 0, c1 = 0, c2 = 0, c3 = 0;
        #pragma unroll 4
        for (int f = 0; f < 128; ++f) {
            float pj = s_oap[l * 129 + f];
            c0 = fmaf(s_t[(r0 + 0) * 128 + f], pj, c0);
            c1 = fmaf(s_t[(r0 + 1) * 128 + f], pj, c1);
            c2 = fmaf(s_t[(r0 + 2) * 128 + f], pj, c2);
            c3 = fmaf(s_t[(r0 + 3) * 128 + f], pj, c3);
        }
        s_sp[(r0 + 0) * 33 + l] = c0;  s_sp[(r0 + 1) * 33 + l] = c1;
        s_sp[(r0 + 2) * 33 + l] = c2;  s_sp[(r0 + 3) * 33 + l] = c3;
    }
    __syncthreads();

    // --- column softmaxes ---
    {
        #pragma unroll
        for (int k = 0; k < 4; ++k) {
            int a = w + 8 * k;
            float v  = s_sc[l * 33 + a] * SOFTMAX_SCALE;
            float m  = warp_max(v);
            float e  = expf(v - m);
            float s  = warp_sum(e);
            float wg = e / s;
            s_w[a * 32 + l] = wg;
            out[WOFF + ((size_t)b * 32 + a) * 32 + l] = wg;
            float v2 = s_sp[l * 33 + a] * SOFTMAX_SCALE;
            float m2 = warp_max(v2);
            float e2 = expf(v2 - m2);
            float s2 = warp_sum(e2);
            s_wp[l * 33 + a] = e2 / s2;
        }
    }
    __syncthreads();

    // === va -> A1 ; vp -> V(gmem) ; avp -> C1 ===
    ull a1regs[4];
    {
        ull av[4][2] = {{0,0},{0,0},{0,0},{0,0}};
        #pragma unroll 1
        for (int ck = 0; ck < 4; ++ck) {
            STAGE(Wv + ck * 4096);
            mm_chunk128(s_oa, 129, ck * 32, s_Wst, av, r0, l);
        }
        ull va_pre[4][2];
        #pragma unroll
        for (int r = 0; r < 4; ++r) { va_pre[r][0] = av[r][0]; va_pre[r][1] = av[r][1]; }
        store128(s_t, av, r0, l, true);

        {
            ull acc[4] = {0, 0, 0, 0};
            #pragma unroll 1
            for (int ck = 0; ck < 2; ++ck) {
                STAGE(Wf1 + ck * 4096);
                mm_chunk64(s_t, ck * 64, s_Wst, acc, r0, l);
            }
            #pragma unroll
            for (int r = 0; r < 4; ++r) {
                a1regs[r] = acc[r];
                *reinterpret_cast<float2*>(&s_A1[(r0 + r) * 64 + 2 * l]) = upk2(acc[r]);
            }
        }

        {
            STAGE(Wv + 96 * 128);
            #pragma unroll 4
            for (int e = 0; e < 32; ++e) {
                ulonglong2 wv = *reinterpret_cast<const ulonglong2*>(&s_Wst[e * 128 + 4 * l]);
                #pragma unroll
                for (int r = 0; r < 4; ++r) {
                    ull xx = pk2(__shfl_sync(0xffffffffu, d_r[r], e));
                    va_pre[r][0] = ffma2(xx, wv.x, va_pre[r][0]);
                    va_pre[r][1] = ffma2(xx, wv.y, va_pre[r][1]);
                }
            }
            store128(s_t, va_pre, r0, l, true);
        }

        {
            ull acc[4] = {0, 0, 0, 0};
            #pragma unroll 1
            for (int ck = 0; ck < 2; ++ck) {
                STAGE(Wf1 + ck * 4096);
                mm_chunk64(s_t, ck * 64, s_Wst, acc, r0, l);
            }
            float* gV = g_V + (size_t)b * 2048;
            #pragma unroll
            for (int r = 0; r < 4; ++r) {
                float2 p = upk2(acc[r]);
                float2 a = upk2(a1regs[r]);
                *reinterpret_cast<float2*>(&gV[(r0 + r) * 64 + 2 * l]) =
                    make_float2((p.x - a.x) * 0.03125f, (p.y - a.y) * 0.03125f);
            }
        }

        {
            ull ap[4][2] = {{0,0},{0,0},{0,0},{0,0}};
            #pragma unroll 1
            for (int ck = 0; ck < 4; ++ck) {
                STAGE(Wvp + ck * 4096);
                mm_chunk128(s_oap, 129, ck * 32, s_Wst, ap, r0, l);
            }
            store128(s_t, ap, r0, l, true);
            ull acc[4] = {0, 0, 0, 0};
            #pragma unroll 1
            for (int ck = 0; ck < 2; ++ck) {
                STAGE(Wf1 + 8192 + ck * 4096);
                mm_chunk64(s_t, ck * 64, s_Wst, acc, r0, l);
            }
            #pragma unroll
            for (int r = 0; r < 4; ++r)
                *reinterpret_cast<float2*>(&s_C1[(r0 + r) * 64 + 2 * l]) = upk2(acc[r]);
        }
    }
    __syncthreads();

    for (int idx = t; idx < 1024; idx += 256)
        out[WPOFF + (size_t)b * 1024 + idx] = s_wp[(idx >> 5) * 33 + (idx & 31)];

    {
        const ull* A1u = reinterpret_cast<const ull*>(s_A1);
        const ull* C1u = reinterpret_cast<const ull*>(s_C1);
        ull uacc[4] = {0, 0, 0, 0};
        #pragma unroll 4
        for (int j = 0; j < 32; ++j) {
            ull wv = A1u[j * 32 + l];
            #pragma unroll
            for (int r = 0; r < 4; ++r)
                uacc[r] = ffma2(pk2(s_w[(r0 + r) * 32 + j]), wv, uacc[r]);
        }
        #pragma unroll 4
        for (int p = 0; p < 32; ++p) {
            ull wv = C1u[p * 32 + l];
            #pragma unroll
            for (int r = 0; r < 4; ++r)
                uacc[r] = ffma2(pk2(s_wp[(r0 + r) * 33 + p]), wv, uacc[r]);
        }
        float* gU = g_U + (size_t)b * 2048;
        #pragma unroll
        for (int r = 0; r < 4; ++r) {
            float2 p = upk2(uacc[r]);
            *reinterpret_cast<float2*>(&gU[(r0 + r) * 64 + 2 * l]) =
                make_float2(p.x * 0.03125f, p.y * 0.03125f);
        }
    }
}

// ---------------------------------------------------------------------------
// Kernel 2: 512 blocks x 512 threads; block = (batch, agent-half), warp = agent.
// <=64 regs -> 2 blocks/SM = 32 warps/SM; waves 1.73; prologues/batch 2.
// ---------------------------------------------------------------------------
extern "C" __global__ void __launch_bounds__(512, 2)
k2_value(float* __restrict__ out) {
    __shared__ float    sV [32 * 68];
    __shared__ float    sU [16 * 64];
    __shared__ float    swt[16 * 33];
    __shared__ unsigned sW2h[64 * 36];
    __shared__ unsigned sW2l[64 * 36];

    const int t  = threadIdx.x;
    const int b  = blockIdx.x >> 1;
    const int a0 = (blockIdx.x & 1) * 16;

    for (int idx = t; idx < 2048; idx += 512) {
        int i = idx >> 6, f = idx & 63;
        sV[i * 68 + f] = g_V[(size_t)b * 2048 + idx];
    }
    for (int idx = t; idx < 1024; idx += 512)
        sU[idx] = g_U[(size_t)b * 2048 + a0 * 64 + idx];
    {
        int a = t >> 5, i = t & 31;           // a = 0..15 for t < 512
        swt[a * 33 + i] = out[WOFF + ((size_t)b * 32 + a0 + a) * 32 + i];
    }
    for (int idx = t; idx < 2048; idx += 512) {
        int f = idx >> 5, n = idx & 31;
        sW2h[f * 36 + n] = g_W2h[idx];
        sW2l[f * 36 + n] = g_W2l[idx];
    }
    __syncthreads();

    const int w = t >> 5, l = t & 31;     // w = 0..15: agent a0 + w
    const int lq = l >> 2;
    const int lr = l & 3;
    const float* Urow = &sU [w * 64];
    const float* wrow = &swt[w * 33];

    float wm[2][2];
    #pragma unroll
    for (int mt = 0; mt < 2; ++mt) {
        wm[mt][0] = wrow[mt * 16 + lq];
        wm[mt][1] = wrow[mt * 16 + lq + 8];
    }

    float D[2][4][4];
    #pragma unroll
    for (int mt = 0; mt < 2; ++mt)
        #pragma unroll
        for (int nt = 0; nt < 4; ++nt)
            #pragma unroll
            for (int q = 0; q < 4; ++q) D[mt][nt][q] = 0.f;

    #pragma unroll
    for (int kt = 0; kt < 8; ++kt) {
        const int f1 = kt * 8 + lr;
        const float U0 = Urow[kt * 8 + lr];      // in-loop LDS keeps regs <= 64
        const float U1 = Urow[kt * 8 + lr + 4];
        unsigned Ah[2][4], Al[2][4];
        #pragma unroll
        for (int mt = 0; mt < 2; ++mt) {
            const int i1 = mt * 16 + lq;
            float v00 = sV[i1 * 68 + f1];
            float v10 = sV[(i1 + 8) * 68 + f1];
            float v01 = sV[i1 * 68 + f1 + 4];
            float v11 = sV[(i1 + 8) * 68 + f1 + 4];
            float h0 = fmaf(wm[mt][0], v00, U0);
            float h1 = fmaf(wm[mt][1], v10, U0);
            float h2 = fmaf(wm[mt][0], v01, U1);
            float h3 = fmaf(wm[mt][1], v11, U1);
            h0 = fmaxf(h0, 0.f) + 0.01f * fminf(h0, 0.f);
            h1 = fmaxf(h1, 0.f) + 0.01f * fminf(h1, 0.f);
            h2 = fmaxf(h2, 0.f) + 0.01f * fminf(h2, 0.f);
            h3 = fmaxf(h3, 0.f) + 0.01f * fminf(h3, 0.f);
            Ah[mt][0] = tf32_of(h0);
            Ah[mt][1] = tf32_of(h1);
            Ah[mt][2] = tf32_of(h2);
            Ah[mt][3] = tf32_of(h3);
            Al[mt][0] = tf32_of(h0 - __uint_as_float(Ah[mt][0]));
            Al[mt][1] = tf32_of(h1 - __uint_as_float(Ah[mt][1]));
            Al[mt][2] = tf32_of(h2 - __uint_as_float(Ah[mt][2]));
            Al[mt][3] = tf32_of(h3 - __uint_as_float(Ah[mt][3]));
        }
        #pragma unroll
        for (int nt = 0; nt < 4; ++nt) {
            const int bo = f1 * 36 + nt * 8 + lq;
            unsigned b0h = sW2h[bo], b1h = sW2h[bo + 4 * 36];
            unsigned b0l = sW2l[bo], b1l = sW2l[bo + 4 * 36];
            #pragma unroll
            for (int mt = 0; mt < 2; ++mt) {
                mma_tf32(D[mt][nt], Ah[mt], b0h, b1h);
                mma_tf32(D[mt][nt], Ah[mt], b0l, b1l);
                mma_tf32(D[mt][nt], Al[mt], b0h, b1h);
            }
        }
    }

    const size_t base = (((size_t)b * 32) + a0 + w) * 1024;
    #pragma unroll
    for (int mt = 0; mt < 2; ++mt) {
        #pragma unroll
        for (int nt = 0; nt < 4; ++nt) {
            const int i1 = mt * 16 + lq;
            const int n  = nt * 8 + 2 * lr;
            *reinterpret_cast<float2*>(&out[base + i1 * 32 + n]) =
                make_float2(D[mt][nt][0], D[mt][nt][1]);
            *reinterpret_cast<float2*>(&out[base + (i1 + 8) * 32 + n]) =
                make_float2(D[mt][nt][2], D[mt][nt][3]);
        }
    }
}

// ---------------------------------------------------------------------------
extern "C" void kernel_launch(void* const* d_in, const int* in_sizes, int n_in,
                              void* d_out, int out_size) {
    const float* states         = (const float*)d_in[0];
    const float* policies       = (const float*)d_in[1];
    const float* actions        = (const float*)d_in[2];
    const float* states_people  = (const float*)d_in[3];
    const float* actions_people = (const float*)d_in[4];
    const float* Wk  = (const float*)d_in[5];
    const float* Wq  = (const float*)d_in[6];
    const float* Wv  = (const float*)d_in[7];
    const float* Wkp = (const float*)d_in[8];
    const float* Wqp = (const float*)d_in[9];
    const float* Wvp = (const float*)d_in[10];
    const float* Wf1 = (const float*)d_in[11];
    const float* Wf2 = (const float*)d_in[12];
    float* out = (float*)d_out;

    k0_all<<<264, 256>>>(Wq, Wk, Wqp, Wkp, Wf2);

    cudaFuncSetAttribute(k1_batch, cudaFuncAttributeMaxDynamicSharedMemorySize, SM1_BYTES);
    k1_batch<<<256, 256, SM1_BYTES>>>(states, policies, actions,
                                      states_people, actions_people,
                                      Wv, Wvp, Wf1, out);

    k2_value<<<512, 512>>>(out);
}

// round 15
// speedup vs baseline: 1.0485x; 1.0485x over previous
#include <cuda_runtime.h>
#include <math.h>

#define BB   256

// out layout: value [B,32,32,32] | weight [B,32,32] | wp [B,32,32]
#define WOFF      (8388608ull)
#define WPOFF     (8650752ull)

typedef unsigned long long ull;

__device__ float g_M [128 * 128];
__device__ float g_Mp[128 * 128];
__device__ float g_U [BB * 32 * 64];
__device__ float g_V [BB * 32 * 64];
__device__ unsigned g_W2bh[32 * 32];   // [k-pair][n] packed bf16x2 (hi split)
__device__ unsigned g_W2bl[32 * 32];   // lo split

// ---- packed f32x2 helpers ----
__device__ __forceinline__ ull pk2(float v) {
    ull r; asm("mov.b64 %0, {%1, %1};" : "=l"(r) : "f"(v)); return r;
}
__device__ __forceinline__ ull ffma2(ull a, ull b, ull c) {
    ull d; asm("fma.rn.f32x2 %0, %1, %2, %3;" : "=l"(d) : "l"(a), "l"(b), "l"(c)); return d;
}
__device__ __forceinline__ float2 upk2(ull v) {
    float2 f; asm("mov.b64 {%0, %1}, %2;" : "=f"(f.x), "=f"(f.y) : "l"(v)); return f;
}

// ---- bf16 helpers ----
// pack two floats as bf16x2: lo -> bits[15:0], hi -> bits[31:16]
__device__ __forceinline__ unsigned bf2(float lo, float hi) {
    unsigned r;
    asm("cvt.rn.bf16x2.f32 %0, %1, %2;" : "=r"(r) : "f"(hi), "f"(lo));
    return r;
}
// 2-way bf16 split: x = hi + lo (each bf16), packed pairwise
__device__ __forceinline__ void bsplit2(float x0, float x1, unsigned& hi, unsigned& lo) {
    hi = bf2(x0, x1);
    float r0 = x0 - __uint_as_float(hi << 16);
    float r1 = x1 - __uint_as_float(hi & 0xFFFF0000u);
    lo = bf2(r0, r1);
}
__device__ __forceinline__ void mma_bf16(float d[4], const unsigned a[4],
                                         unsigned b0, unsigned b1) {
    asm("mma.sync.aligned.m16n8k16.row.col.f32.bf16.bf16.f32 "
        "{%0,%1,%2,%3}, {%4,%5,%6,%7}, {%8,%9}, {%0,%1,%2,%3};"
        : "+f"(d[0]), "+f"(d[1]), "+f"(d[2]), "+f"(d[3])
        : "r"(a[0]), "r"(a[1]), "r"(a[2]), "r"(a[3]), "r"(b0), "r"(b1));
}

__device__ __forceinline__ float warp_max(float v) {
    #pragma unroll
    for (int o = 16; o; o >>= 1) v = fmaxf(v, __shfl_xor_sync(0xffffffffu, v, o));
    return v;
}
__device__ __forceinline__ float warp_sum(float v) {
    #pragma unroll
    for (int o = 16; o; o >>= 1) v += __shfl_xor_sync(0xffffffffu, v, o);
    return v;
}

// ---------------------------------------------------------------------------
// Kernel 0: M/Mp GEMMs (blocks 0..255) + W2 bf16 pair-split (blocks 256..259).
// ---------------------------------------------------------------------------
__global__ void k0_all(const float* __restrict__ Wq, const float* __restrict__ Wk,
                       const float* __restrict__ Wqp, const float* __restrict__ Wkp,
                       const float* __restrict__ Wf2) {
    const int bx = blockIdx.x;
    const int t  = threadIdx.x;
    if (bx >= 256) {
        int idx = (bx - 256) * 256 + t;          // 0..1023 = [k-pair p][n]
        int p = idx >> 5, n = idx & 31;
        float w0 = Wf2[(2 * p) * 32 + n];
        float w1 = Wf2[(2 * p + 1) * 32 + n];
        unsigned hi, lo;
        bsplit2(w0, w1, hi, lo);
        g_W2bh[idx] = hi;
        g_W2bl[idx] = lo;
        return;
    }
    __shared__ float sA[8 * 128];
    __shared__ float sB[16 * 129];
    __shared__ float sR[128 * 2];
    const int mat = bx >> 7;
    const int e0  = ((bx >> 3) & 15) * 8;
    const int c0  = (bx & 7) * 16;
    const float* A  = mat ? Wqp : Wq;
    const float* Bm = mat ? Wkp : Wk;
    float* out      = mat ? g_Mp : g_M;
    for (int i = t; i < 1024; i += 256) sA[i] = A[e0 * 128 + i];
    for (int i = t; i < 2048; i += 256) {
        int r = i >> 7, d = i & 127;
        sB[r * 129 + d] = Bm[(c0 + r) * 128 + d];
    }
    __syncthreads();
    const int kh = t >> 7, r = (t >> 4) & 7, c = t & 15;
    float acc = 0.f;
    const int d0 = kh * 64;
    #pragma unroll 8
    for (int d = 0; d < 64; ++d)
        acc = fmaf(sA[r * 128 + d0 + d], sB[c * 129 + d0 + d], acc);
    sR[(r * 16 + c) * 2 + kh] = acc;
    __syncthreads();
    if (t < 128) {
        int rr = t >> 4, cc = t & 15;
        out[(e0 + rr) * 128 + c0 + cc] = sR[t * 2] + sR[t * 2 + 1];
    }
}

// ---------------------------------------------------------------------------
// k1 staged fp32 GEMM cores (round-7 proven, untouched).
// ---------------------------------------------------------------------------
__device__ __forceinline__ void mm_chunk128(const float* __restrict__ X, int xstr, int e0,
                                            const float* __restrict__ Ws,
                                            ull acc[4][2], int r0, int l) {
    #pragma unroll 4
    for (int e = 0; e < 32; ++e) {
        ulonglong2 wv = *reinterpret_cast<const ulonglong2*>(&Ws[e * 128 + 4 * l]);
        #pragma unroll
        for (int r = 0; r < 4; ++r) {
            ull xx = pk2(X[(r0 + r) * xstr + e0 + e]);
            acc[r][0] = ffma2(xx, wv.x, acc[r][0]);
            acc[r][1] = ffma2(xx, wv.y, acc[r][1]);
        }
    }
}

__device__ __forceinline__ void mm_chunk64(const float* __restrict__ X, int e0,
                                           const float* __restrict__ Ws,
                                           ull acc[4], int r0, int l) {
    #pragma unroll 4
    for (int e = 0; e < 64; ++e) {
        ull wv = *reinterpret_cast<const ull*>(&Ws[e * 64 + 2 * l]);
        #pragma unroll
        for (int r = 0; r < 4; ++r)
            acc[r] = ffma2(pk2(X[(r0 + r) * 128 + e0 + e]), wv, acc[r]);
    }
}

__device__ __forceinline__ void store128(float* __restrict__ Y, ull acc[4][2],
                                         int r0, int l, bool do_tanh) {
    #pragma unroll
    for (int r = 0; r < 4; ++r) {
        float2 p0 = upk2(acc[r][0]);
        float2 p1 = upk2(acc[r][1]);
        float4 v = make_float4(p0.x, p0.y, p1.x, p1.y);
        if (do_tanh) { v.x = tanhf(v.x); v.y = tanhf(v.y); v.z = tanhf(v.z); v.w = tanhf(v.w); }
        *reinterpret_cast<float4*>(&Y[(r0 + r) * 128 + 4 * l]) = v;
    }
}

// ---------------------------------------------------------------------------
// Kernel 1 (round-7 exact): one block per batch. smem = 90,496 B.
// ---------------------------------------------------------------------------
#define SM1_BYTES 90496
#define SOFTMAX_SCALE 0.08838834764831843f   // 1/sqrt(128)

#define STAGE(SRC) do {                                                    \
    __syncthreads();                                                       \
    { const float4* s4 = reinterpret_cast<const float4*>(SRC);            \
      float4* d4 = reinterpret_cast<float4*>(s_Wst);                      \
      for (int i = t; i < 1024; i += 256) d4[i] = s4[i]; }                \
    __syncthreads();                                                       \
} while (0)

extern "C" __global__ void __launch_bounds__(256, 2)
k1_batch(const float* __restrict__ states, const float* __restrict__ policies,
         const float* __restrict__ actions, const float* __restrict__ states_people,
         const float* __restrict__ actions_people,
         const float* __restrict__ Wv, const float* __restrict__ Wvp,
         const float* __restrict__ Wf1, float* __restrict__ out) {
    extern __shared__ __align__(16) float sm[];
    float* s_oa  = sm;                 // 32 x 129
    float* s_oap = s_oa  + 4128;       // 32 x 129
    float* s_t   = s_oap + 4128;       // 32 x 128
    float* s_w   = s_t   + 4096;       // 32 x 32
    float* s_wp  = s_w   + 1024;       // 32 x 33
    float* s_A1  = s_wp  + 1056;       // 32 x 64  (early: sc 32x33)
    float* s_C1  = s_A1  + 2048;       // 32 x 64  (early: sp 32x33)
    float* s_Wst = s_C1  + 2048;       // 4096 floats: weight chunk buffer
    float* s_sc  = s_A1;
    float* s_sp  = s_C1;

    const int b = blockIdx.x;
    const int t = threadIdx.x;
    const int w = t >> 5, l = t & 31, r0 = 4 * w;

    const float* ac = actions  + (size_t)b * 1024;
    const float* po = policies + (size_t)b * 1024;

    float d_r[4];
    #pragma unroll
    for (int r = 0; r < 4; ++r)
        d_r[r] = po[(r0 + r) * 32 + l] - ac[(r0 + r) * 32 + l];

    {
        const float* st  = states         + (size_t)b * 32 * 96;
        const float* stp = states_people  + (size_t)b * 32 * 96;
        const float* acp = actions_people + (size_t)b * 1024;
        for (int idx = t; idx < 4096; idx += 256) {
            int i = idx >> 7, c = idx & 127;
            s_oa [i * 129 + c] = (c < 96) ? st [i * 96 + c] : ac [i * 32 + c - 96];
            s_oap[i * 129 + c] = (c < 96) ? stp[i * 96 + c] : acp[i * 32 + c - 96];
        }
    }

    // --- t = oa @ M (staged); scores -> sc ---
    {
        ull a1[4][2] = {{0,0},{0,0},{0,0},{0,0}};
        #pragma unroll 1
        for (int ck = 0; ck < 4; ++ck) {
            STAGE(g_M + ck * 4096);
            mm_chunk128(s_oa, 129, ck * 32, s_Wst, a1, r0, l);
        }
        store128(s_t, a1, r0, l, false);
        float a0 = 0, s1 = 0, s2 = 0, s3 = 0;
        #pragma unroll 4
        for (int f = 0; f < 128; ++f) {
            float oj = s_oa[l * 129 + f];
            a0 = fmaf(s_t[(r0 + 0) * 128 + f], oj, a0);
            s1 = fmaf(s_t[(r0 + 1) * 128 + f], oj, s1);
            s2 = fmaf(s_t[(r0 + 2) * 128 + f], oj, s2);
            s3 = fmaf(s_t[(r0 + 3) * 128 + f], oj, s3);
        }
        s_sc[(r0 + 0) * 33 + l] = a0;  s_sc[(r0 + 1) * 33 + l] = s1;
        s_sc[(r0 + 2) * 33 + l] = s2;  s_sc[(r0 + 3) * 33 + l] = s3;
    }

    // --- tp = oa @ Mp (staged); scores_p -> sp ---
    {
        ull a2[4][2] = {{0,0},{0,0},{0,0},{0,0}};
        #pragma unroll 1
        for (int ck = 0; ck < 4; ++ck) {
            STAGE(g_Mp + ck * 4096);
            mm_chunk128(s_oa, 129, ck * 32, s_Wst, a2, r0, l);
        }
        store128(s_t, a2, r0, l, false);
        float c0 = 0, c1 = 0, c2 = 0, c3 = 0;
        #pragma unroll 4
        for (int f = 0; f < 128; ++f) {
            float pj = s_oap[l * 129 + f];
            c0 = fmaf(s_t[(r0 + 0) * 128 + f], pj, c0);
            c1 = fmaf(s_t[(r0 + 1) * 128 + f], pj, c1);
            c2 = fmaf(s_t[(r0 + 2) * 128 + f], pj, c2);
            c3 = fmaf(s_t[(r0 + 3) * 128 + f], pj, c3);
        }
        s_sp[(r0 + 0) * 33 + l] = c0;  s_sp[(r0 + 1) * 33 + l] = c1;
        s_sp[(r0 + 2) * 33 + l] = c2;  s_sp[(r0 + 3) * 33 + l] = c3;
    }
    __syncthreads();

    // --- column softmaxes ---
    {
        #pragma unroll
        for (int k = 0; k < 4; ++k) {
            int a = w + 8 * k;
            float v  = s_sc[l * 33 + a] * SOFTMAX_SCALE;
            float m  = warp_max(v);
            float e  = expf(v - m);
            float s  = warp_sum(e);
            float wg = e / s;
            s_w[a * 32 + l] = wg;
            out[WOFF + ((size_t)b * 32 + a) * 32 + l] = wg;
            float v2 = s_sp[l * 33 + a] * SOFTMAX_SCALE;
            float m2 = warp_max(v2);
            float e2 = expf(v2 - m2);
            float s2 = warp_sum(e2);
            s_wp[l * 33 + a] = e2 / s2;
        }
    }
    __syncthreads();

    // === va -> A1 ; vp -> V(gmem) ; avp -> C1 ===
    ull a1regs[4];
    {
        ull av[4][2] = {{0,0},{0,0},{0,0},{0,0}};
        #pragma unroll 1
        for (int ck = 0; ck < 4; ++ck) {
            STAGE(Wv + ck * 4096);
            mm_chunk128(s_oa, 129, ck * 32, s_Wst, av, r0, l);
        }
        ull va_pre[4][2];
        #pragma unroll
        for (int r = 0; r < 4; ++r) { va_pre[r][0] = av[r][0]; va_pre[r][1] = av[r][1]; }
        store128(s_t, av, r0, l, true);

        {
            ull acc[4] = {0, 0, 0, 0};
            #pragma unroll 1
            for (int ck = 0; ck < 2; ++ck) {
                STAGE(Wf1 + ck * 4096);
                mm_chunk64(s_t, ck * 64, s_Wst, acc, r0, l);
            }
            #pragma unroll
            for (int r = 0; r < 4; ++r) {
                a1regs[r] = acc[r];
                *reinterpret_cast<float2*>(&s_A1[(r0 + r) * 64 + 2 * l]) = upk2(acc[r]);
            }
        }

        {
            STAGE(Wv + 96 * 128);
            #pragma unroll 4
            for (int e = 0; e < 32; ++e) {
                ulonglong2 wv = *reinterpret_cast<const ulonglong2*>(&s_Wst[e * 128 + 4 * l]);
                #pragma unroll
                for (int r = 0; r < 4; ++r) {
                    ull xx = pk2(__shfl_sync(0xffffffffu, d_r[r], e));
                    va_pre[r][0] = ffma2(xx, wv.x, va_pre[r][0]);
                    va_pre[r][1] = ffma2(xx, wv.y, va_pre[r][1]);
                }
            }
            store128(s_t, va_pre, r0, l, true);
        }

        {
            ull acc[4] = {0, 0, 0, 0};
            #pragma unroll 1
            for (int ck = 0; ck < 2; ++ck) {
                STAGE(Wf1 + ck * 4096);
                mm_chunk64(s_t, ck * 64, s_Wst, acc, r0, l);
            }
            float* gV = g_V + (size_t)b * 2048;
            #pragma unroll
            for (int r = 0; r < 4; ++r) {
                float2 p = upk2(acc[r]);
                float2 a = upk2(a1regs[r]);
                *reinterpret_cast<float2*>(&gV[(r0 + r) * 64 + 2 * l]) =
                    make_float2((p.x - a.x) * 0.03125f, (p.y - a.y) * 0.03125f);
            }
        }

        {
            ull ap[4][2] = {{0,0},{0,0},{0,0},{0,0}};
            #pragma unroll 1
            for (int ck = 0; ck < 4; ++ck) {
                STAGE(Wvp + ck * 4096);
                mm_chunk128(s_oap, 129, ck * 32, s_Wst, ap, r0, l);
            }
            store128(s_t, ap, r0, l, true);
            ull acc[4] = {0, 0, 0, 0};
            #pragma unroll 1
            for (int ck = 0; ck < 2; ++ck) {
                STAGE(Wf1 + 8192 + ck * 4096);
                mm_chunk64(s_t, ck * 64, s_Wst, acc, r0, l);
            }
            #pragma unroll
            for (int r = 0; r < 4; ++r)
                *reinterpret_cast<float2*>(&s_C1[(r0 + r) * 64 + 2 * l]) = upk2(acc[r]);
        }
    }
    __syncthreads();

    for (int idx = t; idx < 1024; idx += 256)
        out[WPOFF + (size_t)b * 1024 + idx] = s_wp[(idx >> 5) * 33 + (idx & 31)];

    {
        const ull* A1u = reinterpret_cast<const ull*>(s_A1);
        const ull* C1u = reinterpret_cast<const ull*>(s_C1);
        ull uacc[4] = {0, 0, 0, 0};
        #pragma unroll 4
        for (int j = 0; j < 32; ++j) {
            ull wv = A1u[j * 32 + l];
            #pragma unroll
            for (int r = 0; r < 4; ++r)
                uacc[r] = ffma2(pk2(s_w[(r0 + r) * 32 + j]), wv, uacc[r]);
        }
        #pragma unroll 4
        for (int p = 0; p < 32; ++p) {
            ull wv = C1u[p * 32 + l];
            #pragma unroll
            for (int r = 0; r < 4; ++r)
                uacc[r] = ffma2(pk2(s_wp[(r0 + r) * 33 + p]), wv, uacc[r]);
        }
        float* gU = g_U + (size_t)b * 2048;
        #pragma unroll
        for (int r = 0; r < 4; ++r) {
            float2 p = upk2(uacc[r]);
            *reinterpret_cast<float2*>(&gU[(r0 + r) * 64 + 2 * l]) =
                make_float2(p.x * 0.03125f, p.y * 0.03125f);
        }
    }
}

// ---------------------------------------------------------------------------
// Kernel 2: 3xBF16 m16n8k16 value GEMM (half the MMA work of 3xTF32).
// grid 1024 (b, a-quad); warp = agent. Fragment layout (row.col):
//   A: a0={h[lq][2lr],h[lq][2lr+1]} a1={h[lq+8][..]} a2/a3 at k+8.
//   B: b0=pairs(k=2lr) b1=pairs(k=2lr+8), n=lq.
// ---------------------------------------------------------------------------
extern "C" __global__ void __launch_bounds__(256)
k2_value(float* __restrict__ out) {
    __shared__ float    sV [32 * 68];
    __shared__ float    sU [8 * 64];
    __shared__ float    swt[8 * 33];
    __shared__ unsigned sW2h[32 * 36];   // [k-pair][n] stride 36 (conflict-free)
    __shared__ unsigned sW2l[32 * 36];

    const int t  = threadIdx.x;
    const int b  = blockIdx.x >> 2;
    const int a0 = (blockIdx.x & 3) * 8;

    for (int idx = t; idx < 2048; idx += 256) {
        int i = idx >> 6, f = idx & 63;
        sV[i * 68 + f] = g_V[(size_t)b * 2048 + idx];
    }
    for (int idx = t; idx < 512; idx += 256)
        sU[idx] = g_U[(size_t)b * 2048 + a0 * 64 + idx];
    {
        int a = t >> 5, i = t & 31;
        swt[a * 33 + i] = out[WOFF + ((size_t)b * 32 + a0 + a) * 32 + i];
    }
    for (int idx = t; idx < 1024; idx += 256) {
        int p = idx >> 5, n = idx & 31;
        sW2h[p * 36 + n] = g_W2bh[idx];
        sW2l[p * 36 + n] = g_W2bl[idx];
    }
    __syncthreads();

    const int w = t >> 5, l = t & 31;
    const int lq = l >> 2;
    const int lr = l & 3;
    const float* Urow = &sU [w * 64];
    const float* wrow = &swt[w * 33];

    float wm[2][2];
    #pragma unroll
    for (int mt = 0; mt < 2; ++mt) {
        wm[mt][0] = wrow[mt * 16 + lq];
        wm[mt][1] = wrow[mt * 16 + lq + 8];
    }

    float D[2][4][4];
    #pragma unroll
    for (int mt = 0; mt < 2; ++mt)
        #pragma unroll
        for (int nt = 0; nt < 4; ++nt)
            #pragma unroll
            for (int q = 0; q < 4; ++q) D[mt][nt][q] = 0.f;

    #pragma unroll
    for (int kt = 0; kt < 4; ++kt) {
        const int k0 = kt * 16;
        const int ca = k0 + 2 * lr;        // k-pair A (cols ca, ca+1)
        const int cb = ca + 8;             // k-pair B
        float2 Ua = *reinterpret_cast<const float2*>(&Urow[ca]);
        float2 Ub = *reinterpret_cast<const float2*>(&Urow[cb]);

        unsigned Ah[2][4], Al[2][4];
        #pragma unroll
        for (int mt = 0; mt < 2; ++mt) {
            const int i1 = mt * 16 + lq;
            float2 vA0 = *reinterpret_cast<const float2*>(&sV[i1 * 68 + ca]);
            float2 vA1 = *reinterpret_cast<const float2*>(&sV[(i1 + 8) * 68 + ca]);
            float2 vB0 = *reinterpret_cast<const float2*>(&sV[i1 * 68 + cb]);
            float2 vB1 = *reinterpret_cast<const float2*>(&sV[(i1 + 8) * 68 + cb]);
            float h00 = fmaf(wm[mt][0], vA0.x, Ua.x);
            float h01 = fmaf(wm[mt][0], vA0.y, Ua.y);
            float h10 = fmaf(wm[mt][1], vA1.x, Ua.x);
            float h11 = fmaf(wm[mt][1], vA1.y, Ua.y);
            float h20 = fmaf(wm[mt][0], vB0.x, Ub.x);
            float h21 = fmaf(wm[mt][0], vB0.y, Ub.y);
            float h30 = fmaf(wm[mt][1], vB1.x, Ub.x);
            float h31 = fmaf(wm[mt][1], vB1.y, Ub.y);
            h00 = fmaxf(h00, 0.f) + 0.01f * fminf(h00, 0.f);
            h01 = fmaxf(h01, 0.f) + 0.01f * fminf(h01, 0.f);
            h10 = fmaxf(h10, 0.f) + 0.01f * fminf(h10, 0.f);
            h11 = fmaxf(h11, 0.f) + 0.01f * fminf(h11, 0.f);
            h20 = fmaxf(h20, 0.f) + 0.01f * fminf(h20, 0.f);
            h21 = fmaxf(h21, 0.f) + 0.01f * fminf(h21, 0.f);
            h30 = fmaxf(h30, 0.f) + 0.01f * fminf(h30, 0.f);
            h31 = fmaxf(h31, 0.f) + 0.01f * fminf(h31, 0.f);
            bsplit2(h00, h01, Ah[mt][0], Al[mt][0]);
            bsplit2(h10, h11, Ah[mt][1], Al[mt][1]);
            bsplit2(h20, h21, Ah[mt][2], Al[mt][2]);
            bsplit2(h30, h31, Ah[mt][3], Al[mt][3]);
        }
        #pragma unroll
        for (int nt = 0; nt < 4; ++nt) {
            const int n = nt * 8 + lq;
            unsigned b0h = sW2h[(kt * 8 + lr)     * 36 + n];
            unsigned b1h = sW2h[(kt * 8 + lr + 4) * 36 + n];
            unsigned b0l = sW2l[(kt * 8 + lr)     * 36 + n];
            unsigned b1l = sW2l[(kt * 8 + lr + 4) * 36 + n];
            #pragma unroll
            for (int mt = 0; mt < 2; ++mt) {
                mma_bf16(D[mt][nt], Ah[mt], b0h, b1h);
                mma_bf16(D[mt][nt], Ah[mt], b0l, b1l);
                mma_bf16(D[mt][nt], Al[mt], b0h, b1h);
            }
        }
    }

    const size_t base = (((size_t)b * 32) + a0 + w) * 1024;
    #pragma unroll
    for (int mt = 0; mt < 2; ++mt) {
        #pragma unroll
        for (int nt = 0; nt < 4; ++nt) {
            const int i1 = mt * 16 + lq;
            const int n  = nt * 8 + 2 * lr;
            *reinterpret_cast<float2*>(&out[base + i1 * 32 + n]) =
                make_float2(D[mt][nt][0], D[mt][nt][1]);
            *reinterpret_cast<float2*>(&out[base + (i1 + 8) * 32 + n]) =
                make_float2(D[mt][nt][2], D[mt][nt][3]);
        }
    }
}

// ---------------------------------------------------------------------------
extern "C" void kernel_launch(void* const* d_in, const int* in_sizes, int n_in,
                              void* d_out, int out_size) {
    const float* states         = (const float*)d_in[0];
    const float* policies       = (const float*)d_in[1];
    const float* actions        = (const float*)d_in[2];
    const float* states_people  = (const float*)d_in[3];
    const float* actions_people = (const float*)d_in[4];
    const float* Wk  = (const float*)d_in[5];
    const float* Wq  = (const float*)d_in[6];
    const float* Wv  = (const float*)d_in[7];
    const float* Wkp = (const float*)d_in[8];
    const float* Wqp = (const float*)d_in[9];
    const float* Wvp = (const float*)d_in[10];
    const float* Wf1 = (const float*)d_in[11];
    const float* Wf2 = (const float*)d_in[12];
    float* out = (float*)d_out;

    k0_all<<<260, 256>>>(Wq, Wk, Wqp, Wkp, Wf2);

    cudaFuncSetAttribute(k1_batch, cudaFuncAttributeMaxDynamicSharedMemorySize, SM1_BYTES);
    k1_batch<<<256, 256, SM1_BYTES>>>(states, policies, actions,
                                      states_people, actions_people,
                                      Wv, Wvp, Wf1, out);

    k2_value<<<1024, 256>>>(out);
}

// round 16
// speedup vs baseline: 1.3866x; 1.3225x over previous
#include <cuda_runtime.h>
#include <math.h>

#define BB   256

// out layout: value [B,32,32,32] | weight [B,32,32] | wp [B,32,32]
#define WOFF      (8388608ull)
#define WPOFF     (8650752ull)

typedef unsigned long long ull;

// fp32 M/Mp from k0a; packed bf16 hi/lo splits ([k-pair][n]) from k0_pack
__device__ float g_M [128 * 128];
__device__ float g_Mp[128 * 128];
__device__ unsigned g_Mbh [64 * 128], g_Mbl [64 * 128];
__device__ unsigned g_Mpbh[64 * 128], g_Mpbl[64 * 128];
__device__ unsigned g_Wvbh[64 * 128], g_Wvbl[64 * 128];
__device__ unsigned g_Wvpbh[64 * 128], g_Wvpbl[64 * 128];
__device__ unsigned g_Wf1bh[128 * 64], g_Wf1bl[128 * 64];
__device__ unsigned g_W2bh[32 * 32],  g_W2bl[32 * 32];
__device__ float g_U[BB * 32 * 64];
__device__ float g_V[BB * 32 * 64];

// ---- packed f32x2 helpers (U-step) ----
__device__ __forceinline__ ull pk2(float v) {
    ull r; asm("mov.b64 %0, {%1, %1};" : "=l"(r) : "f"(v)); return r;
}
__device__ __forceinline__ ull ffma2(ull a, ull b, ull c) {
    ull d; asm("fma.rn.f32x2 %0, %1, %2, %3;" : "=l"(d) : "l"(a), "l"(b), "l"(c)); return d;
}
__device__ __forceinline__ float2 upk2(ull v) {
    float2 f; asm("mov.b64 {%0, %1}, %2;" : "=f"(f.x), "=f"(f.y) : "l"(v)); return f;
}

// ---- bf16 helpers ----
__device__ __forceinline__ unsigned bf2(float lo, float hi) {
    unsigned r;
    asm("cvt.rn.bf16x2.f32 %0, %1, %2;" : "=r"(r) : "f"(hi), "f"(lo));
    return r;
}
__device__ __forceinline__ void bsplit2(float x0, float x1, unsigned& hi, unsigned& lo) {
    hi = bf2(x0, x1);
    float r0 = x0 - __uint_as_float(hi << 16);
    float r1 = x1 - __uint_as_float(hi & 0xFFFF0000u);
    lo = bf2(r0, r1);
}
__device__ __forceinline__ void mma_bf16(float d[4], const unsigned a[4],
                                         unsigned b0, unsigned b1) {
    asm("mma.sync.aligned.m16n8k16.row.col.f32.bf16.bf16.f32 "
        "{%0,%1,%2,%3}, {%4,%5,%6,%7}, {%8,%9}, {%0,%1,%2,%3};"
        : "+f"(d[0]), "+f"(d[1]), "+f"(d[2]), "+f"(d[3])
        : "r"(a[0]), "r"(a[1]), "r"(a[2]), "r"(a[3]), "r"(b0), "r"(b1));
}
__device__ __forceinline__ void mma3b(float d[4], const unsigned ah[4], const unsigned al[4],
                                      unsigned b0h, unsigned b1h, unsigned b0l, unsigned b1l) {
    mma_bf16(d, ah, b0h, b1h);
    mma_bf16(d, ah, b0l, b1l);
    mma_bf16(d, al, b0h, b1h);
}

__device__ __forceinline__ float warp_max(float v) {
    #pragma unroll
    for (int o = 16; o; o >>= 1) v = fmaxf(v, __shfl_xor_sync(0xffffffffu, v, o));
    return v;
}
__device__ __forceinline__ float warp_sum(float v) {
    #pragma unroll
    for (int o = 16; o; o >>= 1) v += __shfl_xor_sync(0xffffffffu, v, o);
    return v;
}

// ---------------------------------------------------------------------------
// Kernel 0a: M = Wq@Wk^T, Mp = Wqp@Wkp^T (fp32). 256 blocks (round-9 layout).
// ---------------------------------------------------------------------------
__global__ void k0_gemm(const float* __restrict__ Wq, const float* __restrict__ Wk,
                        const float* __restrict__ Wqp, const float* __restrict__ Wkp) {
    __shared__ float sA[8 * 128];
    __shared__ float sB[16 * 129];
    __shared__ float sR[128 * 2];
    const int bx = blockIdx.x;
    const int t  = threadIdx.x;
    const int mat = bx >> 7;
    const int e0  = ((bx >> 3) & 15) * 8;
    const int c0  = (bx & 7) * 16;
    const float* A  = mat ? Wqp : Wq;
    const float* Bm = mat ? Wkp : Wk;
    float* out      = mat ? g_Mp : g_M;
    for (int i = t; i < 1024; i += 256) sA[i] = A[e0 * 128 + i];
    for (int i = t; i < 2048; i += 256) {
        int r = i >> 7, d = i & 127;
        sB[r * 129 + d] = Bm[(c0 + r) * 128 + d];
    }
    __syncthreads();
    const int kh = t >> 7, r = (t >> 4) & 7, c = t & 15;
    float acc = 0.f;
    const int d0 = kh * 64;
    #pragma unroll 8
    for (int d = 0; d < 64; ++d)
        acc = fmaf(sA[r * 128 + d0 + d], sB[c * 129 + d0 + d], acc);
    sR[(r * 16 + c) * 2 + kh] = acc;
    __syncthreads();
    if (t < 128) {
        int rr = t >> 4, cc = t & 15;
        out[(e0 + rr) * 128 + c0 + cc] = sR[t * 2] + sR[t * 2 + 1];
    }
}

// ---------------------------------------------------------------------------
// Kernel 0b: pack all weights to bf16 hi/lo pairs. 164 blocks x 256.
// ---------------------------------------------------------------------------
__global__ void k0_pack(const float* __restrict__ Wv, const float* __restrict__ Wvp,
                        const float* __restrict__ Wf1, const float* __restrict__ Wf2) {
    int idx = blockIdx.x * 256 + threadIdx.x;
    if (idx >= 41984) return;
    const float* src; unsigned* dh; unsigned* dl; int r, sh;
    if (idx < 8192)       { src = g_M;  dh = g_Mbh;  dl = g_Mbl;  r = idx;         sh = 7; }
    else if (idx < 16384) { src = g_Mp; dh = g_Mpbh; dl = g_Mpbl; r = idx - 8192;  sh = 7; }
    else if (idx < 24576) { src = Wv;   dh = g_Wvbh; dl = g_Wvbl; r = idx - 16384; sh = 7; }
    else if (idx < 32768) { src = Wvp;  dh = g_Wvpbh;dl = g_Wvpbl;r = idx - 24576; sh = 7; }
    else if (idx < 40960) { src = Wf1;  dh = g_Wf1bh;dl = g_Wf1bl;r = idx - 32768; sh = 6; }
    else                  { src = Wf2;  dh = g_W2bh; dl = g_W2bl; r = idx - 40960; sh = 5; }
    int ncols = 1 << sh;
    int p = r >> sh, n = r & (ncols - 1);
    float f0 = src[(2 * p) * ncols + n];
    float f1 = src[(2 * p + 1) * ncols + n];
    unsigned h, l;
    bsplit2(f0, f1, h, l);
    dh[r] = h;
    dl[r] = l;
}

// ---------------------------------------------------------------------------
// k1 bf16 MMA cores. lq = l>>2, lr = l&3. A/X packed [32 rows][68 pairs].
// Staged B: sBh/sBl [16 pairs][136].
// ---------------------------------------------------------------------------
__device__ __forceinline__ void stage128(const unsigned* __restrict__ srcH,
                                         const unsigned* __restrict__ srcL, int ck,
                                         unsigned* __restrict__ sBh,
                                         unsigned* __restrict__ sBl, int t) {
    __syncthreads();
    const unsigned* sh = srcH + ck * 2048;
    const unsigned* sl = srcL + ck * 2048;
    for (int i = t; i < 2048; i += 256) {
        int p = i >> 7, n = i & 127;
        sBh[p * 136 + n] = sh[i];
        sBl[p * 136 + n] = sl[i];
    }
    __syncthreads();
}

__device__ __forceinline__ void stage64(const unsigned* __restrict__ srcH,
                                        const unsigned* __restrict__ srcL, int ck,
                                        unsigned* __restrict__ sBh,
                                        unsigned* __restrict__ sBl, int t) {
    __syncthreads();
    const unsigned* sh = srcH + ck * 1024;
    const unsigned* sl = srcL + ck * 1024;
    for (int i = t; i < 1024; i += 256) {
        int p = i >> 6, n = i & 63;
        sBh[p * 136 + n] = sh[i];
        sBl[p * 136 + n] = sl[i];
    }
    __syncthreads();
}

// load A fragments for one (mt, ktile): base pair kp
__device__ __forceinline__ void loadAfrag(const unsigned* __restrict__ Xh,
                                          const unsigned* __restrict__ Xl,
                                          int mt, int kp, int lq, int lr,
                                          unsigned ah[4], unsigned al[4]) {
    const int ra = (mt * 16 + lq) * 68;
    const int rb = ra + 8 * 68;
    ah[0] = Xh[ra + kp + lr];     al[0] = Xl[ra + kp + lr];
    ah[1] = Xh[rb + kp + lr];     al[1] = Xl[rb + kp + lr];
    ah[2] = Xh[ra + kp + lr + 4]; al[2] = Xl[ra + kp + lr + 4];
    ah[3] = Xh[rb + kp + lr + 4]; al[3] = Xl[rb + kp + lr + 4];
}

// 32x128 GEMM: D[2 mt][2 nt][4] += X[32,128] @ W[128,128]
__device__ void tc128(const unsigned* __restrict__ Xh, const unsigned* __restrict__ Xl,
                      const unsigned* __restrict__ gWh, const unsigned* __restrict__ gWl,
                      float D[2][2][4], unsigned* __restrict__ sBh,
                      unsigned* __restrict__ sBl, int w, int lq, int lr, int t) {
    #pragma unroll 1
    for (int ck = 0; ck < 4; ++ck) {
        stage128(gWh, gWl, ck, sBh, sBl, t);
        #pragma unroll
        for (int ktl = 0; ktl < 2; ++ktl) {
            const int kp = ck * 16 + ktl * 8;
            unsigned ah[2][4], al[2][4];
            loadAfrag(Xh, Xl, 0, kp, lq, lr, ah[0], al[0]);
            loadAfrag(Xh, Xl, 1, kp, lq, lr, ah[1], al[1]);
            #pragma unroll
            for (int nt = 0; nt < 2; ++nt) {
                const int n = 16 * w + nt * 8 + lq;
                unsigned b0h = sBh[(ktl * 8 + lr) * 136 + n];
                unsigned b1h = sBh[(ktl * 8 + lr + 4) * 136 + n];
                unsigned b0l = sBl[(ktl * 8 + lr) * 136 + n];
                unsigned b1l = sBl[(ktl * 8 + lr + 4) * 136 + n];
                mma3b(D[0][nt], ah[0], al[0], b0h, b1h, b0l, b1l);
                mma3b(D[1][nt], ah[1], al[1], b0h, b1h, b0l, b1l);
            }
        }
    }
}

// 32x64 GEMM: D[2 mt][4] = X[32,128] @ W[128,64]; warp n-tile = w. ck0: pair offset/16.
__device__ void tc64(const unsigned* __restrict__ Xh, const unsigned* __restrict__ Xl,
                     const unsigned* __restrict__ gWh, const unsigned* __restrict__ gWl,
                     int ck0, float D[2][4], unsigned* __restrict__ sBh,
                     unsigned* __restrict__ sBl, int w, int lq, int lr, int t) {
    #pragma unroll 1
    for (int ck = 0; ck < 4; ++ck) {
        stage64(gWh, gWl, ck0 + ck, sBh, sBl, t);
        #pragma unroll
        for (int ktl = 0; ktl < 2; ++ktl) {
            const int kp = ck * 16 + ktl * 8;
            unsigned ah[2][4], al[2][4];
            loadAfrag(Xh, Xl, 0, kp, lq, lr, ah[0], al[0]);
            loadAfrag(Xh, Xl, 1, kp, lq, lr, ah[1], al[1]);
            const int n = 8 * w + lq;
            unsigned b0h = sBh[(ktl * 8 + lr) * 136 + n];
            unsigned b1h = sBh[(ktl * 8 + lr + 4) * 136 + n];
            unsigned b0l = sBl[(ktl * 8 + lr) * 136 + n];
            unsigned b1l = sBl[(ktl * 8 + lr + 4) * 136 + n];
            mma3b(D[0], ah[0], al[0], b0h, b1h, b0l, b1l);
            mma3b(D[1], ah[1], al[1], b0h, b1h, b0l, b1l);
        }
    }
}

// store D (optionally tanh) into packed t-buffer [32][68]
__device__ __forceinline__ void storeT(unsigned* __restrict__ Th, unsigned* __restrict__ Tl,
                                       const float D[2][2][4], int w, int lq, int lr,
                                       bool do_tanh) {
    #pragma unroll
    for (int mt = 0; mt < 2; ++mt)
        #pragma unroll
        for (int nt = 0; nt < 2; ++nt) {
            const int pair = 8 * w + nt * 4 + lr;
            const int r1 = mt * 16 + lq, r2 = r1 + 8;
            float v0 = D[mt][nt][0], v1 = D[mt][nt][1];
            float v2 = D[mt][nt][2], v3 = D[mt][nt][3];
            if (do_tanh) { v0 = tanhf(v0); v1 = tanhf(v1); v2 = tanhf(v2); v3 = tanhf(v3); }
            unsigned h, l;
            bsplit2(v0, v1, h, l);
            Th[r1 * 68 + pair] = h; Tl[r1 * 68 + pair] = l;
            bsplit2(v2, v3, h, l);
            Th[r2 * 68 + pair] = h; Tl[r2 * 68 + pair] = l;
        }
}

// scores SC[i][j] = sum_f A[i,f] * B[j,f]; warp -> tile (mt=w>>2, nt=w&3)
__device__ void tcScores(const unsigned* __restrict__ Ah_, const unsigned* __restrict__ Al_,
                         const unsigned* __restrict__ Bh_, const unsigned* __restrict__ Bl_,
                         float* __restrict__ SC, int w, int lq, int lr) {
    const int mt = w >> 2, nt = w & 3;
    float Ds[4] = {0.f, 0.f, 0.f, 0.f};
    const int ra = (mt * 16 + lq) * 68;
    const int rb = ra + 8 * 68;
    const int rn = (nt * 8 + lq) * 68;
    #pragma unroll
    for (int kt = 0; kt < 8; ++kt) {
        const int kp = kt * 8;
        unsigned ah[4], al[4];
        ah[0] = Ah_[ra + kp + lr];     al[0] = Al_[ra + kp + lr];
        ah[1] = Ah_[rb + kp + lr];     al[1] = Al_[rb + kp + lr];
        ah[2] = Ah_[ra + kp + lr + 4]; al[2] = Al_[ra + kp + lr + 4];
        ah[3] = Ah_[rb + kp + lr + 4]; al[3] = Al_[rb + kp + lr + 4];
        unsigned b0h = Bh_[rn + kp + lr];
        unsigned b1h = Bh_[rn + kp + lr + 4];
        unsigned b0l = Bl_[rn + kp + lr];
        unsigned b1l = Bl_[rn + kp + lr + 4];
        mma3b(Ds, ah, al, b0h, b1h, b0l, b1l);
    }
    const int i = mt * 16 + lq, j = nt * 8 + 2 * lr;
    SC[i * 33 + j]           = Ds[0];
    SC[i * 33 + j + 1]       = Ds[1];
    SC[(i + 8) * 33 + j]     = Ds[2];
    SC[(i + 8) * 33 + j + 1] = Ds[3];
}

// ---------------------------------------------------------------------------
// Kernel 1: one block per batch, bf16 tensor-core. smem = 99,968 B.
// ---------------------------------------------------------------------------
#define SM1_BYTES 99968
#define SOFTMAX_SCALE 0.08838834764831843f   // 1/sqrt(128)

extern "C" __global__ void __launch_bounds__(256, 2)
k1_batch(const float* __restrict__ states, const float* __restrict__ policies,
         const float* __restrict__ actions, const float* __restrict__ states_people,
         const float* __restrict__ actions_people, float* __restrict__ out) {
    extern __shared__ __align__(16) unsigned smu[];
    unsigned* s_oah  = smu;                  // [32][68]
    unsigned* s_oal  = s_oah  + 2176;
    unsigned* s_oaph = s_oal  + 2176;
    unsigned* s_oapl = s_oaph + 2176;
    unsigned* s_th   = s_oapl + 2176;        // t/tp/va/vp/avp packed
    unsigned* s_tl   = s_th   + 2176;
    unsigned* s_Dh   = s_tl   + 2176;        // [32][20] delta packed
    unsigned* s_Dl   = s_Dh   + 640;
    float* s_w   = reinterpret_cast<float*>(s_Dl + 640);  // [32][32]
    float* s_wp  = s_w  + 1024;              // [32][33]
    float* s_A1  = s_wp + 1056;              // [32][66] fp32 (early: sc [32][33])
    float* s_C1  = s_A1 + 2112;              // [32][66] (early: sp)
    unsigned* sBh = reinterpret_cast<unsigned*>(s_C1 + 2112);  // [16][136]
    unsigned* sBl = sBh + 2176;
    float* s_sc = s_A1;
    float* s_sp = s_C1;

    const int b = blockIdx.x;
    const int t = threadIdx.x;
    const int w = t >> 5, l = t & 31;
    const int lq = l >> 2, lr = l & 3;

    // --- load + pack inputs ---
    {
        const float* st  = states         + (size_t)b * 3072;
        const float* stp = states_people  + (size_t)b * 3072;
        const float* ac  = actions        + (size_t)b * 1024;
        const float* acp = actions_people + (size_t)b * 1024;
        const float* po  = policies       + (size_t)b * 1024;
        for (int idx = t; idx < 2048; idx += 256) {
            int i = idx >> 6, p = idx & 63;
            int c = 2 * p;
            float a0, a1, q0, q1;
            if (c < 96) {
                a0 = st [i * 96 + c]; a1 = st [i * 96 + c + 1];
                q0 = stp[i * 96 + c]; q1 = stp[i * 96 + c + 1];
            } else {
                a0 = ac [i * 32 + c - 96]; a1 = ac [i * 32 + c - 95];
                q0 = acp[i * 32 + c - 96]; q1 = acp[i * 32 + c - 95];
            }
            unsigned h, lo;
            bsplit2(a0, a1, h, lo); s_oah [i * 68 + p] = h; s_oal [i * 68 + p] = lo;
            bsplit2(q0, q1, h, lo); s_oaph[i * 68 + p] = h; s_oapl[i * 68 + p] = lo;
        }
        for (int idx = t; idx < 512; idx += 256) {
            int i = idx >> 4, p = idx & 15;
            int c = 2 * p;
            float d0 = po[i * 32 + c]     - ac[i * 32 + c];
            float d1 = po[i * 32 + c + 1] - ac[i * 32 + c + 1];
            unsigned h, lo;
            bsplit2(d0, d1, h, lo); s_Dh[i * 20 + p] = h; s_Dl[i * 20 + p] = lo;
        }
    }
    // (first stage128 sync orders packing stores)

    // --- t = oa @ M -> scores ---
    {
        float Dt[2][2][4] = {};
        tc128(s_oah, s_oal, g_Mbh, g_Mbl, Dt, sBh, sBl, w, lq, lr, t);
        storeT(s_th, s_tl, Dt, w, lq, lr, false);
        __syncthreads();
        tcScores(s_th, s_tl, s_oah, s_oal, s_sc, w, lq, lr);
    }
    // --- tp = oa @ Mp -> scores_p ---
    {
        float Dtp[2][2][4] = {};
        tc128(s_oah, s_oal, g_Mpbh, g_Mpbl, Dtp, sBh, sBl, w, lq, lr, t);
        storeT(s_th, s_tl, Dtp, w, lq, lr, false);
        __syncthreads();
        tcScores(s_th, s_tl, s_oaph, s_oapl, s_sp, w, lq, lr);
    }
    __syncthreads();

    // --- column softmaxes ---
    {
        #pragma unroll
        for (int k = 0; k < 4; ++k) {
            int a = w + 8 * k;
            float v  = s_sc[l * 33 + a] * SOFTMAX_SCALE;
            float m  = warp_max(v);
            float e  = expf(v - m);
            float s  = warp_sum(e);
            float wg = e / s;
            s_w[a * 32 + l] = wg;
            out[WOFF + ((size_t)b * 32 + a) * 32 + l] = wg;
            float v2 = s_sp[l * 33 + a] * SOFTMAX_SCALE;
            float m2 = warp_max(v2);
            float e2 = expf(v2 - m2);
            float s2 = warp_sum(e2);
            s_wp[l * 33 + a] = e2 / s2;
        }
    }
    // (next stage sync orders softmax reads of sc/sp vs A1/C1 frag stores)

    // === va -> A1 ; vp -> V(gmem) ; avp -> C1 ===
    {
        // va = tanh(oa @ Wv); keep pre-act fragments for vp
        float Dva[2][2][4] = {};
        tc128(s_oah, s_oal, g_Wvbh, g_Wvbl, Dva, sBh, sBl, w, lq, lr, t);
        storeT(s_th, s_tl, Dva, w, lq, lr, true);

        // A1 = va @ Wf1_top (pairs 0..63)
        float DA1[2][4] = {};
        tc64(s_th, s_tl, g_Wf1bh, g_Wf1bl, 0, DA1, sBh, sBl, w, lq, lr, t);
        {
            const int n = 8 * w + 2 * lr;
            #pragma unroll
            for (int mt = 0; mt < 2; ++mt) {
                int r1 = mt * 16 + lq;
                *reinterpret_cast<float2*>(&s_A1[r1 * 66 + n]) =
                    make_float2(DA1[mt][0], DA1[mt][1]);
                *reinterpret_cast<float2*>(&s_A1[(r1 + 8) * 66 + n]) =
                    make_float2(DA1[mt][2], DA1[mt][3]);
            }
        }

        // vp_pre = va_pre + delta @ Wv[96:,:] (pairs 48..63 = chunk 3)
        stage128(g_Wvbh, g_Wvbl, 3, sBh, sBl, t);
        #pragma unroll
        for (int ktl = 0; ktl < 2; ++ktl) {
            const int kp = ktl * 8;
            unsigned ah[2][4], al[2][4];
            #pragma unroll
            for (int mt = 0; mt < 2; ++mt) {
                const int ra = (mt * 16 + lq) * 20;
                const int rb = ra + 8 * 20;
                ah[mt][0] = s_Dh[ra + kp + lr];     al[mt][0] = s_Dl[ra + kp + lr];
                ah[mt][1] = s_Dh[rb + kp + lr];     al[mt][1] = s_Dl[rb + kp + lr];
                ah[mt][2] = s_Dh[ra + kp + lr + 4]; al[mt][2] = s_Dl[ra + kp + lr + 4];
                ah[mt][3] = s_Dh[rb + kp + lr + 4]; al[mt][3] = s_Dl[rb + kp + lr + 4];
            }
            #pragma unroll
            for (int nt = 0; nt < 2; ++nt) {
                const int n = 16 * w + nt * 8 + lq;
                unsigned b0h = sBh[(ktl * 8 + lr) * 136 + n];
                unsigned b1h = sBh[(ktl * 8 + lr + 4) * 136 + n];
                unsigned b0l = sBl[(ktl * 8 + lr) * 136 + n];
                unsigned b1l = sBl[(ktl * 8 + lr + 4) * 136 + n];
                mma3b(Dva[0][nt], ah[0], al[0], b0h, b1h, b0l, b1l);
                mma3b(Dva[1][nt], ah[1], al[1], b0h, b1h, b0l, b1l);
            }
        }
        storeT(s_th, s_tl, Dva, w, lq, lr, true);   // vp

        // B1 = vp @ Wf1_top ; V = (B1 - A1)/32 -> gmem
        float DB1[2][4] = {};
        tc64(s_th, s_tl, g_Wf1bh, g_Wf1bl, 0, DB1, sBh, sBl, w, lq, lr, t);
        {
            float* gV = g_V + (size_t)b * 2048;
            const int n = 8 * w + 2 * lr;
            #pragma unroll
            for (int mt = 0; mt < 2; ++mt) {
                int r1 = mt * 16 + lq;
                *reinterpret_cast<float2*>(&gV[r1 * 64 + n]) =
                    make_float2((DB1[mt][0] - DA1[mt][0]) * 0.03125f,
                                (DB1[mt][1] - DA1[mt][1]) * 0.03125f);
                *reinterpret_cast<float2*>(&gV[(r1 + 8) * 64 + n]) =
                    make_float2((DB1[mt][2] - DA1[mt][2]) * 0.03125f,
                                (DB1[mt][3] - DA1[mt][3]) * 0.03125f);
            }
        }

        // avp = tanh(oap @ Wvp) ; C1 = avp @ Wf1_bot (pairs 64..127)
        float Dap[2][2][4] = {};
        tc128(s_oaph, s_oapl, g_Wvpbh, g_Wvpbl, Dap, sBh, sBl, w, lq, lr, t);
        storeT(s_th, s_tl, Dap, w, lq, lr, true);
        float DC1[2][4] = {};
        tc64(s_th, s_tl, g_Wf1bh, g_Wf1bl, 4, DC1, sBh, sBl, w, lq, lr, t);
        {
            const int n = 8 * w + 2 * lr;
            #pragma unroll
            for (int mt = 0; mt < 2; ++mt) {
                int r1 = mt * 16 + lq;
                *reinterpret_cast<float2*>(&s_C1[r1 * 66 + n]) =
                    make_float2(DC1[mt][0], DC1[mt][1]);
                *reinterpret_cast<float2*>(&s_C1[(r1 + 8) * 66 + n]) =
                    make_float2(DC1[mt][2], DC1[mt][3]);
            }
        }
    }
    __syncthreads();   // A1/C1/w/wp complete; cross-warp reads next

    // --- wp to global ---
    for (int idx = t; idx < 1024; idx += 256)
        out[WPOFF + (size_t)b * 1024 + idx] = s_wp[(idx >> 5) * 33 + (idx & 31)];

    // --- U[a, 2l..2l+1] = (w[a,:]@A1 + wp[a,:]@C1)/32, warp rows 4w..4w+3 ---
    {
        const int r0 = 4 * w;
        const ull* A1u = reinterpret_cast<const ull*>(s_A1);   // stride 33 ull
        const ull* C1u = reinterpret_cast<const ull*>(s_C1);
        ull uacc[4] = {0, 0, 0, 0};
        #pragma unroll 4
        for (int j = 0; j < 32; ++j) {
            ull wv = A1u[j * 33 + l];
            #pragma unroll
            for (int r = 0; r < 4; ++r)
                uacc[r] = ffma2(pk2(s_w[(r0 + r) * 32 + j]), wv, uacc[r]);
        }
        #pragma unroll 4
        for (int p = 0; p < 32; ++p) {
            ull wv = C1u[p * 33 + l];
            #pragma unroll
            for (int r = 0; r < 4; ++r)
                uacc[r] = ffma2(pk2(s_wp[(r0 + r) * 33 + p]), wv, uacc[r]);
        }
        float* gU = g_U + (size_t)b * 2048;
        #pragma unroll
        for (int r = 0; r < 4; ++r) {
            float2 p = upk2(uacc[r]);
            *reinterpret_cast<float2*>(&gU[(r0 + r) * 64 + 2 * l]) =
                make_float2(p.x * 0.03125f, p.y * 0.03125f);
        }
    }
}

// ---------------------------------------------------------------------------
// Kernel 2 (round-15 proven): 3xBF16 m16n8k16 value GEMM.
// ---------------------------------------------------------------------------
extern "C" __global__ void __launch_bounds__(256)
k2_value(float* __restrict__ out) {
    __shared__ float    sV [32 * 68];
    __shared__ float    sU [8 * 64];
    __shared__ float    swt[8 * 33];
    __shared__ unsigned sW2h[32 * 36];
    __shared__ unsigned sW2l[32 * 36];

    const int t  = threadIdx.x;
    const int b  = blockIdx.x >> 2;
    const int a0 = (blockIdx.x & 3) * 8;

    for (int idx = t; idx < 2048; idx += 256) {
        int i = idx >> 6, f = idx & 63;
        sV[i * 68 + f] = g_V[(size_t)b * 2048 + idx];
    }
    for (int idx = t; idx < 512; idx += 256)
        sU[idx] = g_U[(size_t)b * 2048 + a0 * 64 + idx];
    {
        int a = t >> 5, i = t & 31;
        swt[a * 33 + i] = out[WOFF + ((size_t)b * 32 + a0 + a) * 32 + i];
    }
    for (int idx = t; idx < 1024; idx += 256) {
        int p = idx >> 5, n = idx & 31;
        sW2h[p * 36 + n] = g_W2bh[idx];
        sW2l[p * 36 + n] = g_W2bl[idx];
    }
    __syncthreads();

    const int w = t >> 5, l = t & 31;
    const int lq = l >> 2;
    const int lr = l & 3;
    const float* Urow = &sU [w * 64];
    const float* wrow = &swt[w * 33];

    float wm[2][2];
    #pragma unroll
    for (int mt = 0; mt < 2; ++mt) {
        wm[mt][0] = wrow[mt * 16 + lq];
        wm[mt][1] = wrow[mt * 16 + lq + 8];
    }

    float D[2][4][4];
    #pragma unroll
    for (int mt = 0; mt < 2; ++mt)
        #pragma unroll
        for (int nt = 0; nt < 4; ++nt)
            #pragma unroll
            for (int q = 0; q < 4; ++q) D[mt][nt][q] = 0.f;

    #pragma unroll
    for (int kt = 0; kt < 4; ++kt) {
        const int k0 = kt * 16;
        const int ca = k0 + 2 * lr;
        const int cb = ca + 8;
        float2 Ua = *reinterpret_cast<const float2*>(&Urow[ca]);
        float2 Ub = *reinterpret_cast<const float2*>(&Urow[cb]);

        unsigned Ah[2][4], Al[2][4];
        #pragma unroll
        for (int mt = 0; mt < 2; ++mt) {
            const int i1 = mt * 16 + lq;
            float2 vA0 = *reinterpret_cast<const float2*>(&sV[i1 * 68 + ca]);
            float2 vA1 = *reinterpret_cast<const float2*>(&sV[(i1 + 8) * 68 + ca]);
            float2 vB0 = *reinterpret_cast<const float2*>(&sV[i1 * 68 + cb]);
            float2 vB1 = *reinterpret_cast<const float2*>(&sV[(i1 + 8) * 68 + cb]);
            float h00 = fmaf(wm[mt][0], vA0.x, Ua.x);
            float h01 = fmaf(wm[mt][0], vA0.y, Ua.y);
            float h10 = fmaf(wm[mt][1], vA1.x, Ua.x);
            float h11 = fmaf(wm[mt][1], vA1.y, Ua.y);
            float h20 = fmaf(wm[mt][0], vB0.x, Ub.x);
            float h21 = fmaf(wm[mt][0], vB0.y, Ub.y);
            float h30 = fmaf(wm[mt][1], vB1.x, Ub.x);
            float h31 = fmaf(wm[mt][1], vB1.y, Ub.y);
            h00 = fmaxf(h00, 0.f) + 0.01f * fminf(h00, 0.f);
            h01 = fmaxf(h01, 0.f) + 0.01f * fminf(h01, 0.f);
            h10 = fmaxf(h10, 0.f) + 0.01f * fminf(h10, 0.f);
            h11 = fmaxf(h11, 0.f) + 0.01f * fminf(h11, 0.f);
            h20 = fmaxf(h20, 0.f) + 0.01f * fminf(h20, 0.f);
            h21 = fmaxf(h21, 0.f) + 0.01f * fminf(h21, 0.f);
            h30 = fmaxf(h30, 0.f) + 0.01f * fminf(h30, 0.f);
            h31 = fmaxf(h31, 0.f) + 0.01f * fminf(h31, 0.f);
            bsplit2(h00, h01, Ah[mt][0], Al[mt][0]);
            bsplit2(h10, h11, Ah[mt][1], Al[mt][1]);
            bsplit2(h20, h21, Ah[mt][2], Al[mt][2]);
            bsplit2(h30, h31, Ah[mt][3], Al[mt][3]);
        }
        #pragma unroll
        for (int nt = 0; nt < 4; ++nt) {
            const int n = nt * 8 + lq;
            unsigned b0h = sW2h[(kt * 8 + lr)     * 36 + n];
            unsigned b1h = sW2h[(kt * 8 + lr + 4) * 36 + n];
            unsigned b0l = sW2l[(kt * 8 + lr)     * 36 + n];
            unsigned b1l = sW2l[(kt * 8 + lr + 4) * 36 + n];
            #pragma unroll
            for (int mt = 0; mt < 2; ++mt) {
                mma_bf16(D[mt][nt], Ah[mt], b0h, b1h);
                mma_bf16(D[mt][nt], Ah[mt], b0l, b1l);
                mma_bf16(D[mt][nt], Al[mt], b0h, b1h);
            }
        }
    }

    const size_t base = (((size_t)b * 32) + a0 + w) * 1024;
    #pragma unroll
    for (int mt = 0; mt < 2; ++mt) {
        #pragma unroll
        for (int nt = 0; nt < 4; ++nt) {
            const int i1 = mt * 16 + lq;
            const int n  = nt * 8 + 2 * lr;
            *reinterpret_cast<float2*>(&out[base + i1 * 32 + n]) =
                make_float2(D[mt][nt][0], D[mt][nt][1]);
            *reinterpret_cast<float2*>(&out[base + (i1 + 8) * 32 + n]) =
                make_float2(D[mt][nt][2], D[mt][nt][3]);
        }
    }
}

// ---------------------------------------------------------------------------
extern "C" void kernel_launch(void* const* d_in, const int* in_sizes, int n_in,
                              void* d_out, int out_size) {
    const float* states         = (const float*)d_in[0];
    const float* policies       = (const float*)d_in[1];
    const float* actions        = (const float*)d_in[2];
    const float* states_people  = (const float*)d_in[3];
    const float* actions_people = (const float*)d_in[4];
    const float* Wk  = (const float*)d_in[5];
    const float* Wq  = (const float*)d_in[6];
    const float* Wv  = (const float*)d_in[7];
    const float* Wkp = (const float*)d_in[8];
    const float* Wqp = (const float*)d_in[9];
    const float* Wvp = (const float*)d_in[10];
    const float* Wf1 = (const float*)d_in[11];
    const float* Wf2 = (const float*)d_in[12];
    float* out = (float*)d_out;

    k0_gemm<<<256, 256>>>(Wq, Wk, Wqp, Wkp);
    k0_pack<<<164, 256>>>(Wv, Wvp, Wf1, Wf2);

    cudaFuncSetAttribute(k1_batch, cudaFuncAttributeMaxDynamicSharedMemorySize, SM1_BYTES);
    k1_batch<<<256, 256, SM1_BYTES>>>(states, policies, actions,
                                      states_people, actions_people, out);

    k2_value<<<1024, 256>>>(out);
}

// round 17
// speedup vs baseline: 1.5145x; 1.0923x over previous
#include <cuda_runtime.h>
#include <math.h>

#define BB   256

// out layout: value [B,32,32,32] | weight [B,32,32] | wp [B,32,32]
#define WOFF      (8388608ull)
#define WPOFF     (8650752ull)

typedef unsigned long long ull;

// packed bf16 hi/lo splits ([k-pair][n]) produced by k0_all
__device__ unsigned g_Mbh [64 * 128], g_Mbl [64 * 128];
__device__ unsigned g_Mpbh[64 * 128], g_Mpbl[64 * 128];
__device__ unsigned g_Wvbh[64 * 128], g_Wvbl[64 * 128];
__device__ unsigned g_Wvpbh[64 * 128], g_Wvpbl[64 * 128];
__device__ unsigned g_Wf1bh[128 * 64], g_Wf1bl[128 * 64];
__device__ unsigned g_W2bh[32 * 32],  g_W2bl[32 * 32];
__device__ float g_U[BB * 32 * 64];
__device__ float g_V[BB * 32 * 64];

// ---- packed f32x2 helpers (U-step) ----
__device__ __forceinline__ ull pk2(float v) {
    ull r; asm("mov.b64 %0, {%1, %1};" : "=l"(r) : "f"(v)); return r;
}
__device__ __forceinline__ ull ffma2(ull a, ull b, ull c) {
    ull d; asm("fma.rn.f32x2 %0, %1, %2, %3;" : "=l"(d) : "l"(a), "l"(b), "l"(c)); return d;
}
__device__ __forceinline__ float2 upk2(ull v) {
    float2 f; asm("mov.b64 {%0, %1}, %2;" : "=f"(f.x), "=f"(f.y) : "l"(v)); return f;
}

// ---- bf16 helpers ----
__device__ __forceinline__ unsigned bf2(float lo, float hi) {
    unsigned r;
    asm("cvt.rn.bf16x2.f32 %0, %1, %2;" : "=r"(r) : "f"(hi), "f"(lo));
    return r;
}
__device__ __forceinline__ void bsplit2(float x0, float x1, unsigned& hi, unsigned& lo) {
    hi = bf2(x0, x1);
    float r0 = x0 - __uint_as_float(hi << 16);
    float r1 = x1 - __uint_as_float(hi & 0xFFFF0000u);
    lo = bf2(r0, r1);
}
__device__ __forceinline__ void mma_bf16(float d[4], const unsigned a[4],
                                         unsigned b0, unsigned b1) {
    asm("mma.sync.aligned.m16n8k16.row.col.f32.bf16.bf16.f32 "
        "{%0,%1,%2,%3}, {%4,%5,%6,%7}, {%8,%9}, {%0,%1,%2,%3};"
        : "+f"(d[0]), "+f"(d[1]), "+f"(d[2]), "+f"(d[3])
        : "r"(a[0]), "r"(a[1]), "r"(a[2]), "r"(a[3]), "r"(b0), "r"(b1));
}
__device__ __forceinline__ void mma3b(float d[4], const unsigned ah[4], const unsigned al[4],
                                      unsigned b0h, unsigned b1h, unsigned b0l, unsigned b1l) {
    mma_bf16(d, ah, b0h, b1h);
    mma_bf16(d, ah, b0l, b1l);
    mma_bf16(d, al, b0h, b1h);
}

__device__ __forceinline__ float warp_max(float v) {
    #pragma unroll
    for (int o = 16; o; o >>= 1) v = fmaxf(v, __shfl_xor_sync(0xffffffffu, v, o));
    return v;
}
__device__ __forceinline__ float warp_sum(float v) {
    #pragma unroll
    for (int o = 16; o; o >>= 1) v += __shfl_xor_sync(0xffffffffu, v, o);
    return v;
}

// ---------------------------------------------------------------------------
// Kernel 0 (merged single launch):
//   blocks 0..255  : M/Mp = Wq@Wk^T / Wqp@Wkp^T, packed bf16 hi/lo directly.
//   blocks 256..355: pack Wv/Wvp/Wf1/Wf2 to bf16 hi/lo pairs.
// ---------------------------------------------------------------------------
__global__ void k0_all(const float* __restrict__ Wq, const float* __restrict__ Wk,
                       const float* __restrict__ Wqp, const float* __restrict__ Wkp,
                       const float* __restrict__ Wv, const float* __restrict__ Wvp,
                       const float* __restrict__ Wf1, const float* __restrict__ Wf2) {
    const int bx = blockIdx.x;
    const int t  = threadIdx.x;
    if (bx >= 256) {
        int idx = (bx - 256) * 256 + t;          // 0..25599 pair-elements
        const float* src; unsigned* dh; unsigned* dl; int r, sh;
        if (idx < 8192)       { src = Wv;  dh = g_Wvbh; dl = g_Wvbl; r = idx;         sh = 7; }
        else if (idx < 16384) { src = Wvp; dh = g_Wvpbh;dl = g_Wvpbl;r = idx - 8192;  sh = 7; }
        else if (idx < 24576) { src = Wf1; dh = g_Wf1bh;dl = g_Wf1bl;r = idx - 16384; sh = 6; }
        else                  { src = Wf2; dh = g_W2bh; dl = g_W2bl; r = idx - 24576; sh = 5; }
        int ncols = 1 << sh;
        int p = r >> sh, n = r & (ncols - 1);
        float f0 = src[(2 * p) * ncols + n];
        float f1 = src[(2 * p + 1) * ncols + n];
        unsigned h, l;
        bsplit2(f0, f1, h, l);
        dh[r] = h;
        dl[r] = l;
        return;
    }
    __shared__ float sA[8 * 128];
    __shared__ float sB[16 * 129];
    __shared__ float sR[128 * 2];
    __shared__ float sT[128];
    const int mat = bx >> 7;
    const int e0  = ((bx >> 3) & 15) * 8;
    const int c0  = (bx & 7) * 16;
    const float* A  = mat ? Wqp : Wq;
    const float* Bm = mat ? Wkp : Wk;
    for (int i = t; i < 1024; i += 256) sA[i] = A[e0 * 128 + i];
    for (int i = t; i < 2048; i += 256) {
        int r = i >> 7, d = i & 127;
        sB[r * 129 + d] = Bm[(c0 + r) * 128 + d];
    }
    __syncthreads();
    const int kh = t >> 7, r = (t >> 4) & 7, c = t & 15;
    float acc = 0.f;
    const int d0 = kh * 64;
    #pragma unroll 8
    for (int d = 0; d < 64; ++d)
        acc = fmaf(sA[r * 128 + d0 + d], sB[c * 129 + d0 + d], acc);
    sR[(r * 16 + c) * 2 + kh] = acc;
    __syncthreads();
    if (t < 128) sT[t] = sR[t * 2] + sR[t * 2 + 1];   // t = rr*16 + cc
    __syncthreads();
    if (t < 64) {
        int p = t >> 4, cc = t & 15;
        float f0 = sT[(2 * p) * 16 + cc];
        float f1 = sT[(2 * p + 1) * 16 + cc];
        unsigned h, l;
        bsplit2(f0, f1, h, l);
        unsigned* dh = mat ? g_Mpbh : g_Mbh;
        unsigned* dl = mat ? g_Mpbl : g_Mbl;
        int dst = ((e0 >> 1) + p) * 128 + c0 + cc;
        dh[dst] = h;
        dl[dst] = l;
    }
}

// ---------------------------------------------------------------------------
// k1 bf16 MMA cores. lq = l>>2, lr = l&3. A/X packed [32 rows][68 pairs].
// Staging buffers sBh/sBl hold 2304 words each; layouts:
//   128-wide chunks: [16 pairs][136]; 64-wide chunks: [32 pairs][72].
// tc128/tc64 prefetch the next chunk into registers during compute.
// ---------------------------------------------------------------------------
__device__ __forceinline__ void stage128(const unsigned* __restrict__ srcH,
                                         const unsigned* __restrict__ srcL, int ck,
                                         unsigned* __restrict__ sBh,
                                         unsigned* __restrict__ sBl, int t) {
    __syncthreads();
    const unsigned* sh = srcH + ck * 2048;
    const unsigned* sl = srcL + ck * 2048;
    for (int i = t; i < 2048; i += 256) {
        int p = i >> 7, n = i & 127;
        sBh[p * 136 + n] = sh[i];
        sBl[p * 136 + n] = sl[i];
    }
    __syncthreads();
}

// load A fragments for one (mt, ktile): base pair kp
__device__ __forceinline__ void loadAfrag(const unsigned* __restrict__ Xh,
                                          const unsigned* __restrict__ Xl,
                                          int mt, int kp, int lq, int lr,
                                          unsigned ah[4], unsigned al[4]) {
    const int ra = (mt * 16 + lq) * 68;
    const int rb = ra + 8 * 68;
    ah[0] = Xh[ra + kp + lr];     al[0] = Xl[ra + kp + lr];
    ah[1] = Xh[rb + kp + lr];     al[1] = Xl[rb + kp + lr];
    ah[2] = Xh[ra + kp + lr + 4]; al[2] = Xl[ra + kp + lr + 4];
    ah[3] = Xh[rb + kp + lr + 4]; al[3] = Xl[rb + kp + lr + 4];
}

// 32x128 GEMM with register-prefetch pipelining (4 chunks of 16 pairs).
__device__ void tc128(const unsigned* __restrict__ Xh, const unsigned* __restrict__ Xl,
                      const unsigned* __restrict__ gWh, const unsigned* __restrict__ gWl,
                      float D[2][2][4], unsigned* __restrict__ sBh,
                      unsigned* __restrict__ sBl, int w, int lq, int lr, int t) {
    uint4 ph0, ph1, pl0, pl1;
    {
        const uint4* h4 = reinterpret_cast<const uint4*>(gWh);
        const uint4* l4 = reinterpret_cast<const uint4*>(gWl);
        ph0 = h4[2 * t]; ph1 = h4[2 * t + 1];
        pl0 = l4[2 * t]; pl1 = l4[2 * t + 1];
    }
    const int sp = t >> 4, scol = (t * 8) & 127;
    #pragma unroll 1
    for (int ck = 0; ck < 4; ++ck) {
        __syncthreads();
        *reinterpret_cast<uint4*>(&sBh[sp * 136 + scol])     = ph0;
        *reinterpret_cast<uint4*>(&sBh[sp * 136 + scol + 4]) = ph1;
        *reinterpret_cast<uint4*>(&sBl[sp * 136 + scol])     = pl0;
        *reinterpret_cast<uint4*>(&sBl[sp * 136 + scol + 4]) = pl1;
        if (ck < 3) {
            const uint4* h4 = reinterpret_cast<const uint4*>(gWh + (ck + 1) * 2048);
            const uint4* l4 = reinterpret_cast<const uint4*>(gWl + (ck + 1) * 2048);
            ph0 = h4[2 * t]; ph1 = h4[2 * t + 1];
            pl0 = l4[2 * t]; pl1 = l4[2 * t + 1];
        }
        __syncthreads();
        #pragma unroll
        for (int ktl = 0; ktl < 2; ++ktl) {
            const int kp = ck * 16 + ktl * 8;
            unsigned ah[2][4], al[2][4];
            loadAfrag(Xh, Xl, 0, kp, lq, lr, ah[0], al[0]);
            loadAfrag(Xh, Xl, 1, kp, lq, lr, ah[1], al[1]);
            #pragma unroll
            for (int nt = 0; nt < 2; ++nt) {
                const int n = 16 * w + nt * 8 + lq;
                unsigned b0h = sBh[(ktl * 8 + lr) * 136 + n];
                unsigned b1h = sBh[(ktl * 8 + lr + 4) * 136 + n];
                unsigned b0l = sBl[(ktl * 8 + lr) * 136 + n];
                unsigned b1l = sBl[(ktl * 8 + lr + 4) * 136 + n];
                mma3b(D[0][nt], ah[0], al[0], b0h, b1h, b0l, b1l);
                mma3b(D[1][nt], ah[1], al[1], b0h, b1h, b0l, b1l);
            }
        }
    }
}

// 32x64 GEMM: 2 chunks of 32 pairs ([32][72] layout). ck0 in 32-pair units.
__device__ void tc64(const unsigned* __restrict__ Xh, const unsigned* __restrict__ Xl,
                     const unsigned* __restrict__ gWh, const unsigned* __restrict__ gWl,
                     int ck0, float D[2][4], unsigned* __restrict__ sBh,
                     unsigned* __restrict__ sBl, int w, int lq, int lr, int t) {
    uint4 ph0, ph1, pl0, pl1;
    {
        const uint4* h4 = reinterpret_cast<const uint4*>(gWh + ck0 * 2048);
        const uint4* l4 = reinterpret_cast<const uint4*>(gWl + ck0 * 2048);
        ph0 = h4[2 * t]; ph1 = h4[2 * t + 1];
        pl0 = l4[2 * t]; pl1 = l4[2 * t + 1];
    }
    const int sp = t >> 3, scol = (t * 8) & 63;
    #pragma unroll 1
    for (int ck = 0; ck < 2; ++ck) {
        __syncthreads();
        *reinterpret_cast<uint4*>(&sBh[sp * 72 + scol])     = ph0;
        *reinterpret_cast<uint4*>(&sBh[sp * 72 + scol + 4]) = ph1;
        *reinterpret_cast<uint4*>(&sBl[sp * 72 + scol])     = pl0;
        *reinterpret_cast<uint4*>(&sBl[sp * 72 + scol + 4]) = pl1;
        if (ck < 1) {
            const uint4* h4 = reinterpret_cast<const uint4*>(gWh + (ck0 + 1) * 2048);
            const uint4* l4 = reinterpret_cast<const uint4*>(gWl + (ck0 + 1) * 2048);
            ph0 = h4[2 * t]; ph1 = h4[2 * t + 1];
            pl0 = l4[2 * t]; pl1 = l4[2 * t + 1];
        }
        __syncthreads();
        #pragma unroll
        for (int ktl = 0; ktl < 4; ++ktl) {
            const int kp = ck * 32 + ktl * 8;
            unsigned ah[2][4], al[2][4];
            loadAfrag(Xh, Xl, 0, kp, lq, lr, ah[0], al[0]);
            loadAfrag(Xh, Xl, 1, kp, lq, lr, ah[1], al[1]);
            const int n = 8 * w + lq;
            unsigned b0h = sBh[(ktl * 8 + lr) * 72 + n];
            unsigned b1h = sBh[(ktl * 8 + lr + 4) * 72 + n];
            unsigned b0l = sBl[(ktl * 8 + lr) * 72 + n];
            unsigned b1l = sBl[(ktl * 8 + lr + 4) * 72 + n];
            mma3b(D[0], ah[0], al[0], b0h, b1h, b0l, b1l);
            mma3b(D[1], ah[1], al[1], b0h, b1h, b0l, b1l);
        }
    }
}

// store D (optionally tanh) into packed t-buffer [32][68]
__device__ __forceinline__ void storeT(unsigned* __restrict__ Th, unsigned* __restrict__ Tl,
                                       const float D[2][2][4], int w, int lq, int lr,
                                       bool do_tanh) {
    #pragma unroll
    for (int mt = 0; mt < 2; ++mt)
        #pragma unroll
        for (int nt = 0; nt < 2; ++nt) {
            const int pair = 8 * w + nt * 4 + lr;
            const int r1 = mt * 16 + lq, r2 = r1 + 8;
            float v0 = D[mt][nt][0], v1 = D[mt][nt][1];
            float v2 = D[mt][nt][2], v3 = D[mt][nt][3];
            if (do_tanh) { v0 = tanhf(v0); v1 = tanhf(v1); v2 = tanhf(v2); v3 = tanhf(v3); }
            unsigned h, l;
            bsplit2(v0, v1, h, l);
            Th[r1 * 68 + pair] = h; Tl[r1 * 68 + pair] = l;
            bsplit2(v2, v3, h, l);
            Th[r2 * 68 + pair] = h; Tl[r2 * 68 + pair] = l;
        }
}

// scores SC[i][j] = sum_f A[i,f] * B[j,f]; warp -> tile (mt=w>>2, nt=w&3)
__device__ void tcScores(const unsigned* __restrict__ Ah_, const unsigned* __restrict__ Al_,
                         const unsigned* __restrict__ Bh_, const unsigned* __restrict__ Bl_,
                         float* __restrict__ SC, int w, int lq, int lr) {
    const int mt = w >> 2, nt = w & 3;
    float Ds[4] = {0.f, 0.f, 0.f, 0.f};
    const int ra = (mt * 16 + lq) * 68;
    const int rb = ra + 8 * 68;
    const int rn = (nt * 8 + lq) * 68;
    #pragma unroll
    for (int kt = 0; kt < 8; ++kt) {
        const int kp = kt * 8;
        unsigned ah[4], al[4];
        ah[0] = Ah_[ra + kp + lr];     al[0] = Al_[ra + kp + lr];
        ah[1] = Ah_[rb + kp + lr];     al[1] = Al_[rb + kp + lr];
        ah[2] = Ah_[ra + kp + lr + 4]; al[2] = Al_[ra + kp + lr + 4];
        ah[3] = Ah_[rb + kp + lr + 4]; al[3] = Al_[rb + kp + lr + 4];
        unsigned b0h = Bh_[rn + kp + lr];
        unsigned b1h = Bh_[rn + kp + lr + 4];
        unsigned b0l = Bl_[rn + kp + lr];
        unsigned b1l = Bl_[rn + kp + lr + 4];
        mma3b(Ds, ah, al, b0h, b1h, b0l, b1l);
    }
    const int i = mt * 16 + lq, j = nt * 8 + 2 * lr;
    SC[i * 33 + j]           = Ds[0];
    SC[i * 33 + j + 1]       = Ds[1];
    SC[(i + 8) * 33 + j]     = Ds[2];
    SC[(i + 8) * 33 + j + 1] = Ds[3];
}

// ---------------------------------------------------------------------------
// Kernel 1: one block per batch, bf16 tensor-core. smem = 100,992 B.
// ---------------------------------------------------------------------------
#define SM1_BYTES 100992
#define SOFTMAX_SCALE 0.08838834764831843f   // 1/sqrt(128)

extern "C" __global__ void __launch_bounds__(256, 2)
k1_batch(const float* __restrict__ states, const float* __restrict__ policies,
         const float* __restrict__ actions, const float* __restrict__ states_people,
         const float* __restrict__ actions_people, float* __restrict__ out) {
    extern __shared__ __align__(16) unsigned smu[];
    unsigned* s_oah  = smu;                  // [32][68]
    unsigned* s_oal  = s_oah  + 2176;
    unsigned* s_oaph = s_oal  + 2176;
    unsigned* s_oapl = s_oaph + 2176;
    unsigned* s_th   = s_oapl + 2176;        // t/tp/va/vp/avp packed
    unsigned* s_tl   = s_th   + 2176;
    unsigned* s_Dh   = s_tl   + 2176;        // [32][20] delta packed
    unsigned* s_Dl   = s_Dh   + 640;
    float* s_w   = reinterpret_cast<float*>(s_Dl + 640);  // [32][32]
    float* s_wp  = s_w  + 1024;              // [32][33]
    float* s_A1  = s_wp + 1056;              // [32][66] fp32 (early: sc [32][33])
    float* s_C1  = s_A1 + 2112;              // [32][66] (early: sp)
    unsigned* sBh = reinterpret_cast<unsigned*>(s_C1 + 2112);  // 2304 words
    unsigned* sBl = sBh + 2304;
    float* s_sc = s_A1;
    float* s_sp = s_C1;

    const int b = blockIdx.x;
    const int t = threadIdx.x;
    const int w = t >> 5, l = t & 31;
    const int lq = l >> 2, lr = l & 3;

    // --- load + pack inputs ---
    {
        const float* st  = states         + (size_t)b * 3072;
        const float* stp = states_people  + (size_t)b * 3072;
        const float* ac  = actions        + (size_t)b * 1024;
        const float* acp = actions_people + (size_t)b * 1024;
        const float* po  = policies       + (size_t)b * 1024;
        for (int idx = t; idx < 2048; idx += 256) {
            int i = idx >> 6, p = idx & 63;
            int c = 2 * p;
            float a0, a1, q0, q1;
            if (c < 96) {
                a0 = st [i * 96 + c]; a1 = st [i * 96 + c + 1];
                q0 = stp[i * 96 + c]; q1 = stp[i * 96 + c + 1];
            } else {
                a0 = ac [i * 32 + c - 96]; a1 = ac [i * 32 + c - 95];
                q0 = acp[i * 32 + c - 96]; q1 = acp[i * 32 + c - 95];
            }
            unsigned h, lo;
            bsplit2(a0, a1, h, lo); s_oah [i * 68 + p] = h; s_oal [i * 68 + p] = lo;
            bsplit2(q0, q1, h, lo); s_oaph[i * 68 + p] = h; s_oapl[i * 68 + p] = lo;
        }
        for (int idx = t; idx < 512; idx += 256) {
            int i = idx >> 4, p = idx & 15;
            int c = 2 * p;
            float d0 = po[i * 32 + c]     - ac[i * 32 + c];
            float d1 = po[i * 32 + c + 1] - ac[i * 32 + c + 1];
            unsigned h, lo;
            bsplit2(d0, d1, h, lo); s_Dh[i * 20 + p] = h; s_Dl[i * 20 + p] = lo;
        }
    }
    // (first tc128 internal sync orders packing stores before A reads)

    // --- t = oa @ M -> scores ---
    {
        float Dt[2][2][4] = {};
        tc128(s_oah, s_oal, g_Mbh, g_Mbl, Dt, sBh, sBl, w, lq, lr, t);
        storeT(s_th, s_tl, Dt, w, lq, lr, false);
        __syncthreads();
        tcScores(s_th, s_tl, s_oah, s_oal, s_sc, w, lq, lr);
    }
    // --- tp = oa @ Mp -> scores_p ---
    {
        float Dtp[2][2][4] = {};
        tc128(s_oah, s_oal, g_Mpbh, g_Mpbl, Dtp, sBh, sBl, w, lq, lr, t);
        storeT(s_th, s_tl, Dtp, w, lq, lr, false);
        __syncthreads();
        tcScores(s_th, s_tl, s_oaph, s_oapl, s_sp, w, lq, lr);
    }
    __syncthreads();

    // --- column softmaxes ---
    {
        #pragma unroll
        for (int k = 0; k < 4; ++k) {
            int a = w + 8 * k;
            float v  = s_sc[l * 33 + a] * SOFTMAX_SCALE;
            float m  = warp_max(v);
            float e  = expf(v - m);
            float s  = warp_sum(e);
            float wg = e / s;
            s_w[a * 32 + l] = wg;
            out[WOFF + ((size_t)b * 32 + a) * 32 + l] = wg;
            float v2 = s_sp[l * 33 + a] * SOFTMAX_SCALE;
            float m2 = warp_max(v2);
            float e2 = expf(v2 - m2);
            float s2 = warp_sum(e2);
            s_wp[l * 33 + a] = e2 / s2;
        }
    }
    // (next tc128 internal sync orders softmax reads of sc/sp before A1/C1 stores)

    // === va -> A1 ; vp -> V(gmem) ; avp -> C1 ===
    {
        // va = tanh(oa @ Wv); keep pre-act fragments for vp
        float Dva[2][2][4] = {};
        tc128(s_oah, s_oal, g_Wvbh, g_Wvbl, Dva, sBh, sBl, w, lq, lr, t);
        storeT(s_th, s_tl, Dva, w, lq, lr, true);

        // A1 = va @ Wf1_top (32-pair chunks 0..1)
        float DA1[2][4] = {};
        tc64(s_th, s_tl, g_Wf1bh, g_Wf1bl, 0, DA1, sBh, sBl, w, lq, lr, t);
        {
            const int n = 8 * w + 2 * lr;
            #pragma unroll
            for (int mt = 0; mt < 2; ++mt) {
                int r1 = mt * 16 + lq;
                *reinterpret_cast<float2*>(&s_A1[r1 * 66 + n]) =
                    make_float2(DA1[mt][0], DA1[mt][1]);
                *reinterpret_cast<float2*>(&s_A1[(r1 + 8) * 66 + n]) =
                    make_float2(DA1[mt][2], DA1[mt][3]);
            }
        }

        // vp_pre = va_pre + delta @ Wv[96:,:] (16-pair chunk 3)
        stage128(g_Wvbh, g_Wvbl, 3, sBh, sBl, t);
        #pragma unroll
        for (int ktl = 0; ktl < 2; ++ktl) {
            const int kp = ktl * 8;
            unsigned ah[2][4], al[2][4];
            #pragma unroll
            for (int mt = 0; mt < 2; ++mt) {
                const int ra = (mt * 16 + lq) * 20;
                const int rb = ra + 8 * 20;
                ah[mt][0] = s_Dh[ra + kp + lr];     al[mt][0] = s_Dl[ra + kp + lr];
                ah[mt][1] = s_Dh[rb + kp + lr];     al[mt][1] = s_Dl[rb + kp + lr];
                ah[mt][2] = s_Dh[ra + kp + lr + 4]; al[mt][2] = s_Dl[ra + kp + lr + 4];
                ah[mt][3] = s_Dh[rb + kp + lr + 4]; al[mt][3] = s_Dl[rb + kp + lr + 4];
            }
            #pragma unroll
            for (int nt = 0; nt < 2; ++nt) {
                const int n = 16 * w + nt * 8 + lq;
                unsigned b0h = sBh[(ktl * 8 + lr) * 136 + n];
                unsigned b1h = sBh[(ktl * 8 + lr + 4) * 136 + n];
                unsigned b0l = sBl[(ktl * 8 + lr) * 136 + n];
                unsigned b1l = sBl[(ktl * 8 + lr + 4) * 136 + n];
                mma3b(Dva[0][nt], ah[0], al[0], b0h, b1h, b0l, b1l);
                mma3b(Dva[1][nt], ah[1], al[1], b0h, b1h, b0l, b1l);
            }
        }
        storeT(s_th, s_tl, Dva, w, lq, lr, true);   // vp

        // B1 = vp @ Wf1_top ; V = (B1 - A1)/32 -> gmem
        float DB1[2][4] = {};
        tc64(s_th, s_tl, g_Wf1bh, g_Wf1bl, 0, DB1, sBh, sBl, w, lq, lr, t);
        {
            float* gV = g_V + (size_t)b * 2048;
            const int n = 8 * w + 2 * lr;
            #pragma unroll
            for (int mt = 0; mt < 2; ++mt) {
                int r1 = mt * 16 + lq;
                *reinterpret_cast<float2*>(&gV[r1 * 64 + n]) =
                    make_float2((DB1[mt][0] - DA1[mt][0]) * 0.03125f,
                                (DB1[mt][1] - DA1[mt][1]) * 0.03125f);
                *reinterpret_cast<float2*>(&gV[(r1 + 8) * 64 + n]) =
                    make_float2((DB1[mt][2] - DA1[mt][2]) * 0.03125f,
                                (DB1[mt][3] - DA1[mt][3]) * 0.03125f);
            }
        }

        // avp = tanh(oap @ Wvp) ; C1 = avp @ Wf1_bot (32-pair chunks 2..3)
        float Dap[2][2][4] = {};
        tc128(s_oaph, s_oapl, g_Wvpbh, g_Wvpbl, Dap, sBh, sBl, w, lq, lr, t);
        storeT(s_th, s_tl, Dap, w, lq, lr, true);
        float DC1[2][4] = {};
        tc64(s_th, s_tl, g_Wf1bh, g_Wf1bl, 2, DC1, sBh, sBl, w, lq, lr, t);
        {
            const int n = 8 * w + 2 * lr;
            #pragma unroll
            for (int mt = 0; mt < 2; ++mt) {
                int r1 = mt * 16 + lq;
                *reinterpret_cast<float2*>(&s_C1[r1 * 66 + n]) =
                    make_float2(DC1[mt][0], DC1[mt][1]);
                *reinterpret_cast<float2*>(&s_C1[(r1 + 8) * 66 + n]) =
                    make_float2(DC1[mt][2], DC1[mt][3]);
            }
        }
    }
    __syncthreads();   // A1/C1/w/wp complete; cross-warp reads next

    // --- wp to global ---
    for (int idx = t; idx < 1024; idx += 256)
        out[WPOFF + (size_t)b * 1024 + idx] = s_wp[(idx >> 5) * 33 + (idx & 31)];

    // --- U[a, 2l..2l+1] = (w[a,:]@A1 + wp[a,:]@C1)/32, warp rows 4w..4w+3 ---
    {
        const int r0 = 4 * w;
        const ull* A1u = reinterpret_cast<const ull*>(s_A1);   // stride 33 ull
        const ull* C1u = reinterpret_cast<const ull*>(s_C1);
        ull uacc[4] = {0, 0, 0, 0};
        #pragma unroll 4
        for (int j = 0; j < 32; ++j) {
            ull wv = A1u[j * 33 + l];
            #pragma unroll
            for (int r = 0; r < 4; ++r)
                uacc[r] = ffma2(pk2(s_w[(r0 + r) * 32 + j]), wv, uacc[r]);
        }
        #pragma unroll 4
        for (int p = 0; p < 32; ++p) {
            ull wv = C1u[p * 33 + l];
            #pragma unroll
            for (int r = 0; r < 4; ++r)
                uacc[r] = ffma2(pk2(s_wp[(r0 + r) * 33 + p]), wv, uacc[r]);
        }
        float* gU = g_U + (size_t)b * 2048;
        #pragma unroll
        for (int r = 0; r < 4; ++r) {
            float2 p = upk2(uacc[r]);
            *reinterpret_cast<float2*>(&gU[(r0 + r) * 64 + 2 * l]) =
                make_float2(p.x * 0.03125f, p.y * 0.03125f);
        }
    }
}

// ---------------------------------------------------------------------------
// Kernel 2 (round-15/16 proven): 3xBF16 m16n8k16 value GEMM.
// ---------------------------------------------------------------------------
extern "C" __global__ void __launch_bounds__(256)
k2_value(float* __restrict__ out) {
    __shared__ float    sV [32 * 68];
    __shared__ float    sU [8 * 64];
    __shared__ float    swt[8 * 33];
    __shared__ unsigned sW2h[32 * 36];
    __shared__ unsigned sW2l[32 * 36];

    const int t  = threadIdx.x;
    const int b  = blockIdx.x >> 2;
    const int a0 = (blockIdx.x & 3) * 8;

    for (int idx = t; idx < 2048; idx += 256) {
        int i = idx >> 6, f = idx & 63;
        sV[i * 68 + f] = g_V[(size_t)b * 2048 + idx];
    }
    for (int idx = t; idx < 512; idx += 256)
        sU[idx] = g_U[(size_t)b * 2048 + a0 * 64 + idx];
    {
        int a = t >> 5, i = t & 31;
        swt[a * 33 + i] = out[WOFF + ((size_t)b * 32 + a0 + a) * 32 + i];
    }
    for (int idx = t; idx < 1024; idx += 256) {
        int p = idx >> 5, n = idx & 31;
        sW2h[p * 36 + n] = g_W2bh[idx];
        sW2l[p * 36 + n] = g_W2bl[idx];
    }
    __syncthreads();

    const int w = t >> 5, l = t & 31;
    const int lq = l >> 2;
    const int lr = l & 3;
    const float* Urow = &sU [w * 64];
    const float* wrow = &swt[w * 33];

    float wm[2][2];
    #pragma unroll
    for (int mt = 0; mt < 2; ++mt) {
        wm[mt][0] = wrow[mt * 16 + lq];
        wm[mt][1] = wrow[mt * 16 + lq + 8];
    }

    float D[2][4][4];
    #pragma unroll
    for (int mt = 0; mt < 2; ++mt)
        #pragma unroll
        for (int nt = 0; nt < 4; ++nt)
            #pragma unroll
            for (int q = 0; q < 4; ++q) D[mt][nt][q] = 0.f;

    #pragma unroll
    for (int kt = 0; kt < 4; ++kt) {
        const int k0 = kt * 16;
        const int ca = k0 + 2 * lr;
        const int cb = ca + 8;
        float2 Ua = *reinterpret_cast<const float2*>(&Urow[ca]);
        float2 Ub = *reinterpret_cast<const float2*>(&Urow[cb]);

        unsigned Ah[2][4], Al[2][4];
        #pragma unroll
        for (int mt = 0; mt < 2; ++mt) {
            const int i1 = mt * 16 + lq;
            float2 vA0 = *reinterpret_cast<const float2*>(&sV[i1 * 68 + ca]);
            float2 vA1 = *reinterpret_cast<const float2*>(&sV[(i1 + 8) * 68 + ca]);
            float2 vB0 = *reinterpret_cast<const float2*>(&sV[i1 * 68 + cb]);
            float2 vB1 = *reinterpret_cast<const float2*>(&sV[(i1 + 8) * 68 + cb]);
            float h00 = fmaf(wm[mt][0], vA0.x, Ua.x);
            float h01 = fmaf(wm[mt][0], vA0.y, Ua.y);
            float h10 = fmaf(wm[mt][1], vA1.x, Ua.x);
            float h11 = fmaf(wm[mt][1], vA1.y, Ua.y);
            float h20 = fmaf(wm[mt][0], vB0.x, Ub.x);
            float h21 = fmaf(wm[mt][0], vB0.y, Ub.y);
            float h30 = fmaf(wm[mt][1], vB1.x, Ub.x);
            float h31 = fmaf(wm[mt][1], vB1.y, Ub.y);
            h00 = fmaxf(h00, 0.f) + 0.01f * fminf(h00, 0.f);
            h01 = fmaxf(h01, 0.f) + 0.01f * fminf(h01, 0.f);
            h10 = fmaxf(h10, 0.f) + 0.01f * fminf(h10, 0.f);
            h11 = fmaxf(h11, 0.f) + 0.01f * fminf(h11, 0.f);
            h20 = fmaxf(h20, 0.f) + 0.01f * fminf(h20, 0.f);
            h21 = fmaxf(h21, 0.f) + 0.01f * fminf(h21, 0.f);
            h30 = fmaxf(h30, 0.f) + 0.01f * fminf(h30, 0.f);
            h31 = fmaxf(h31, 0.f) + 0.01f * fminf(h31, 0.f);
            bsplit2(h00, h01, Ah[mt][0], Al[mt][0]);
            bsplit2(h10, h11, Ah[mt][1], Al[mt][1]);
            bsplit2(h20, h21, Ah[mt][2], Al[mt][2]);
            bsplit2(h30, h31, Ah[mt][3], Al[mt][3]);
        }
        #pragma unroll
        for (int nt = 0; nt < 4; ++nt) {
            const int n = nt * 8 + lq;
            unsigned b0h = sW2h[(kt * 8 + lr)     * 36 + n];
            unsigned b1h = sW2h[(kt * 8 + lr + 4) * 36 + n];
            unsigned b0l = sW2l[(kt * 8 + lr)     * 36 + n];
            unsigned b1l = sW2l[(kt * 8 + lr + 4) * 36 + n];
            #pragma unroll
            for (int mt = 0; mt < 2; ++mt) {
                mma_bf16(D[mt][nt], Ah[mt], b0h, b1h);
                mma_bf16(D[mt][nt], Ah[mt], b0l, b1l);
                mma_bf16(D[mt][nt], Al[mt], b0h, b1h);
            }
        }
    }

    const size_t base = (((size_t)b * 32) + a0 + w) * 1024;
    #pragma unroll
    for (int mt = 0; mt < 2; ++mt) {
        #pragma unroll
        for (int nt = 0; nt < 4; ++nt) {
            const int i1 = mt * 16 + lq;
            const int n  = nt * 8 + 2 * lr;
            *reinterpret_cast<float2*>(&out[base + i1 * 32 + n]) =
                make_float2(D[mt][nt][0], D[mt][nt][1]);
            *reinterpret_cast<float2*>(&out[base + (i1 + 8) * 32 + n]) =
                make_float2(D[mt][nt][2], D[mt][nt][3]);
        }
    }
}

// ---------------------------------------------------------------------------
extern "C" void kernel_launch(void* const* d_in, const int* in_sizes, int n_in,
                              void* d_out, int out_size) {
    const float* states         = (const float*)d_in[0];
    const float* policies       = (const float*)d_in[1];
    const float* actions        = (const float*)d_in[2];
    const float* states_people  = (const float*)d_in[3];
    const float* actions_people = (const float*)d_in[4];
    const float* Wk  = (const float*)d_in[5];
    const float* Wq  = (const float*)d_in[6];
    const float* Wv  = (const float*)d_in[7];
    const float* Wkp = (const float*)d_in[8];
    const float* Wqp = (const float*)d_in[9];
    const float* Wvp = (const float*)d_in[10];
    const float* Wf1 = (const float*)d_in[11];
    const float* Wf2 = (const float*)d_in[12];
    float* out = (float*)d_out;

    k0_all<<<356, 256>>>(Wq, Wk, Wqp, Wkp, Wv, Wvp, Wf1, Wf2);

    cudaFuncSetAttribute(k1_batch, cudaFuncAttributeMaxDynamicSharedMemorySize, SM1_BYTES);
    k1_batch<<<256, 256, SM1_BYTES>>>(states, policies, actions,
                                      states_people, actions_people, out);

    k2_value<<<1024, 256>>>(out);
}